// round 3
// baseline (speedup 1.0000x reference)
#include <cuda_runtime.h>
#include <cstdint>
#include <cstddef>

// Problem dims
#define Nn 256
#define Tt 128
#define Dd 512
#define Hh 1024
#define G4 4096            // 4*H
#define Ktot 2560          // H (h) + H (attn) + D (x_t)

// GEMM tiling
#define BM 128
#define BN 64
#define BK 16
#define APAD 4

// ---------------- scratch (device globals: allocation-free rule) ----------------
__device__ float g_h[Nn * Hh];
__device__ float g_c[Nn * Hh];
__device__ float g_attn[Nn * Hh];
__device__ float g_gates[(size_t)Nn * G4];

// ---------------- math helpers ----------------
__device__ __forceinline__ float sigmoidf_(float x) {
    return 1.0f / (1.0f + __expf(-x));
}
__device__ __forceinline__ float tanhf_(float x) {
    // accurate enough (~1e-6 rel) and robust at extremes
    float e = __expf(2.0f * x);
    return 1.0f - 2.0f / (e + 1.0f);
}

// packed f32x2 FMA (sm_100+): 2 FMAs per instruction, rt_SMSP=2 -> 128 FMA/cyc/SM
__device__ __forceinline__ unsigned long long dupf(float v) {
    unsigned long long d;
    unsigned int u = __float_as_uint(v);
    asm("mov.b64 %0, {%1, %1};" : "=l"(d) : "r"(u));
    return d;
}
__device__ __forceinline__ void ffma2(unsigned long long& a,
                                      unsigned long long x,
                                      unsigned long long y) {
    asm("fma.rn.f32x2 %0, %1, %2, %0;" : "+l"(a) : "l"(x), "l"(y));
}

// =====================================================================
// Per-step GEMM: gates[n, j] = [h | attn | x_t](n, :) @ [Wh; Wattn; Wx](:, j) + b[j]
// M=256, N=4096, K=2560. Grid (64, 2) = 128 blocks, 256 threads.
// =====================================================================
__global__ __launch_bounds__(256) void gemm_step_kernel(
    const float* __restrict__ x,
    const float* __restrict__ Wh,
    const float* __restrict__ Wattn,
    const float* __restrict__ Wx,
    const float* __restrict__ b,
    int t)
{
    __shared__ __align__(16) float As[BK][BM + APAD];
    __shared__ __align__(16) float Bs[BK][BN];

    const int tid = threadIdx.x;
    const int bm = blockIdx.y * BM;
    const int bn = blockIdx.x * BN;

    // A-tile loader: 2 float4 per thread (rows tid/4 and tid/4+64)
    const int arow = tid >> 2;
    const int acol = (tid & 3) * 4;
    // B-tile loader: 1 float4 per thread
    const int brow = tid >> 4;
    const int bcol = (tid & 15) * 4;
    // compute mapping: 16x16 thread grid, each thread -> 8(M) x 4(N) outputs
    const int tx = tid & 15;
    const int ty = tid >> 4;

    unsigned long long acc[4][4];
#pragma unroll
    for (int p = 0; p < 4; p++)
#pragma unroll
        for (int j = 0; j < 4; j++) acc[p][j] = 0ull;

    for (int k0 = 0; k0 < Ktot; k0 += BK) {
        // ---- load A tile (source switches by k-region; BK=16 never crosses boundaries) ----
#pragma unroll
        for (int r = 0; r < 2; r++) {
            int m = arow + r * 64;
            int gm = bm + m;
            const float* ap;
            if (k0 < Hh)          ap = g_h    + (size_t)gm * Hh + k0;
            else if (k0 < 2 * Hh) ap = g_attn + (size_t)gm * Hh + (k0 - Hh);
            else                  ap = x + (size_t)gm * (Tt * Dd) + (size_t)t * Dd + (k0 - 2 * Hh);
            float4 v = *(const float4*)(ap + acol);
            As[acol + 0][m] = v.x;
            As[acol + 1][m] = v.y;
            As[acol + 2][m] = v.z;
            As[acol + 3][m] = v.w;
        }
        // ---- load B tile ----
        {
            int k = k0 + brow;
            const float* bp;
            if (k < Hh)          bp = Wh    + (size_t)k * G4;
            else if (k < 2 * Hh) bp = Wattn + (size_t)(k - Hh) * G4;
            else                 bp = Wx    + (size_t)(k - 2 * Hh) * G4;
            *(float4*)&Bs[brow][bcol] = *(const float4*)(bp + bn + bcol);
        }
        __syncthreads();

#pragma unroll
        for (int k = 0; k < BK; k++) {
            // A as packed f32x2 pairs along M (contiguous in As[k][...])
            ulonglong2 a01 = *(const ulonglong2*)&As[k][ty * 8];
            ulonglong2 a23 = *(const ulonglong2*)&As[k][ty * 8 + 4];
            float4 bv = *(const float4*)&Bs[k][tx * 4];
            unsigned long long b0 = dupf(bv.x), b1 = dupf(bv.y);
            unsigned long long b2 = dupf(bv.z), b3 = dupf(bv.w);

            ffma2(acc[0][0], a01.x, b0); ffma2(acc[0][1], a01.x, b1);
            ffma2(acc[0][2], a01.x, b2); ffma2(acc[0][3], a01.x, b3);
            ffma2(acc[1][0], a01.y, b0); ffma2(acc[1][1], a01.y, b1);
            ffma2(acc[1][2], a01.y, b2); ffma2(acc[1][3], a01.y, b3);
            ffma2(acc[2][0], a23.x, b0); ffma2(acc[2][1], a23.x, b1);
            ffma2(acc[2][2], a23.x, b2); ffma2(acc[2][3], a23.x, b3);
            ffma2(acc[3][0], a23.y, b0); ffma2(acc[3][1], a23.y, b1);
            ffma2(acc[3][2], a23.y, b2); ffma2(acc[3][3], a23.y, b3);
        }
        __syncthreads();
    }

    // ---- epilogue: + bias, write gates ----
#pragma unroll
    for (int p = 0; p < 4; p++) {
        int m = bm + ty * 8 + 2 * p;
#pragma unroll
        for (int j = 0; j < 4; j++) {
            int col = bn + tx * 4 + j;
            float lo = __uint_as_float((unsigned int)(acc[p][j] & 0xffffffffull));
            float hi = __uint_as_float((unsigned int)(acc[p][j] >> 32));
            float bb = b[col];
            g_gates[(size_t)m * G4 + col]       = lo + bb;
            g_gates[(size_t)(m + 1) * G4 + col] = hi + bb;
        }
    }
}

// =====================================================================
// Attention over the 4x4 grid (block-per-n, 256 threads). hs = current h in smem.
// scores_l = (1/32) * sum_h A[n,h,l]*hs[h]; softmax over l; attn_h = sum_l A[n,h,l]*w_l
// =====================================================================
__device__ __forceinline__ void attention_block(int n, const float* __restrict__ A,
                                                const float* hs, float* attn_out, int tid)
{
    __shared__ float red[16][8];
    __shared__ float wsm[16];

    const float* An = A + (size_t)n * Hh * 16;

    float sc[16];
#pragma unroll
    for (int l = 0; l < 16; l++) sc[l] = 0.0f;

#pragma unroll
    for (int r = 0; r < 4; r++) {
        int hh = tid + r * 256;
        float hv = hs[hh];
        const float4* ar = (const float4*)(An + (size_t)hh * 16);
        float4 a0 = ar[0], a1 = ar[1], a2 = ar[2], a3 = ar[3];
        sc[0]  += a0.x * hv; sc[1]  += a0.y * hv; sc[2]  += a0.z * hv; sc[3]  += a0.w * hv;
        sc[4]  += a1.x * hv; sc[5]  += a1.y * hv; sc[6]  += a1.z * hv; sc[7]  += a1.w * hv;
        sc[8]  += a2.x * hv; sc[9]  += a2.y * hv; sc[10] += a2.z * hv; sc[11] += a2.w * hv;
        sc[12] += a3.x * hv; sc[13] += a3.y * hv; sc[14] += a3.z * hv; sc[15] += a3.w * hv;
    }
#pragma unroll
    for (int l = 0; l < 16; l++) {
#pragma unroll
        for (int off = 16; off > 0; off >>= 1)
            sc[l] += __shfl_xor_sync(0xffffffffu, sc[l], off);
    }
    int warp = tid >> 5, lane = tid & 31;
    if (lane == 0) {
#pragma unroll
        for (int l = 0; l < 16; l++) red[l][warp] = sc[l];
    }
    __syncthreads();
    if (tid == 0) {
        float s[16];
        float mx = -1e30f;
#pragma unroll
        for (int l = 0; l < 16; l++) {
            float v = 0.0f;
#pragma unroll
            for (int w = 0; w < 8; w++) v += red[l][w];
            v *= 0.03125f;  // 1/sqrt(1024)
            s[l] = v;
            mx = fmaxf(mx, v);
        }
        float sum = 0.0f;
#pragma unroll
        for (int l = 0; l < 16; l++) { float e = __expf(s[l] - mx); s[l] = e; sum += e; }
        float inv = 1.0f / sum;
#pragma unroll
        for (int l = 0; l < 16; l++) wsm[l] = s[l] * inv;
    }
    __syncthreads();

    float4 w0 = *(float4*)&wsm[0],  w1 = *(float4*)&wsm[4];
    float4 w2 = *(float4*)&wsm[8],  w3 = *(float4*)&wsm[12];
#pragma unroll
    for (int r = 0; r < 4; r++) {
        int hh = tid + r * 256;
        const float4* ar = (const float4*)(An + (size_t)hh * 16);
        float4 a0 = ar[0], a1 = ar[1], a2 = ar[2], a3 = ar[3];
        float v = a0.x * w0.x + a0.y * w0.y + a0.z * w0.z + a0.w * w0.w
                + a1.x * w1.x + a1.y * w1.y + a1.z * w1.z + a1.w * w1.w
                + a2.x * w2.x + a2.y * w2.y + a2.z * w2.z + a2.w * w2.w
                + a3.x * w3.x + a3.y * w3.y + a3.z * w3.z + a3.w * w3.w;
        attn_out[hh] = v;
    }
}

// =====================================================================
// Init: h0 = mean_l A[n,h,l]; c0 = h0; then attention for step 0.
// =====================================================================
__global__ __launch_bounds__(256) void init_kernel(const float* __restrict__ A)
{
    __shared__ float hs[Hh];
    int n = blockIdx.x;
    int tid = threadIdx.x;
    const float* An = A + (size_t)n * Hh * 16;

#pragma unroll
    for (int r = 0; r < 4; r++) {
        int hh = tid + r * 256;
        const float4* ar = (const float4*)(An + (size_t)hh * 16);
        float4 a0 = ar[0], a1 = ar[1], a2 = ar[2], a3 = ar[3];
        float s = a0.x + a0.y + a0.z + a0.w + a1.x + a1.y + a1.z + a1.w
                + a2.x + a2.y + a2.z + a2.w + a3.x + a3.y + a3.z + a3.w;
        s *= (1.0f / 16.0f);
        g_h[(size_t)n * Hh + hh] = s;
        g_c[(size_t)n * Hh + hh] = s;
        hs[hh] = s;
    }
    __syncthreads();
    attention_block(n, A, hs, g_attn + (size_t)n * Hh, tid);
}

// =====================================================================
// LSTM pointwise + next-step attention (fused). Block-per-n, 256 threads.
// =====================================================================
__global__ __launch_bounds__(256) void lstm_attn_kernel(const float* __restrict__ A,
                                                        float* __restrict__ out, int t)
{
    __shared__ float hs[Hh];
    int n = blockIdx.x;
    int tid = threadIdx.x;
    const float* gn = g_gates + (size_t)n * G4;

#pragma unroll
    for (int r = 0; r < 4; r++) {
        int hh = tid + r * 256;
        float iv = gn[hh];
        float fv = gn[Hh + hh];
        float ov = gn[2 * Hh + hh];
        float gv = gn[3 * Hh + hh];
        float c = g_c[(size_t)n * Hh + hh];
        float cn = sigmoidf_(fv) * c + sigmoidf_(iv) * tanhf_(gv);
        float hn = sigmoidf_(ov) * tanhf_(cn);
        g_c[(size_t)n * Hh + hh] = cn;
        g_h[(size_t)n * Hh + hh] = hn;
        out[(size_t)n * Tt * Hh + (size_t)t * Hh + hh] = hn;
        hs[hh] = hn;
    }
    __syncthreads();
    attention_block(n, A, hs, g_attn + (size_t)n * Hh, tid);
}

// =====================================================================
// launch
// =====================================================================
extern "C" void kernel_launch(void* const* d_in, const int* in_sizes, int n_in,
                              void* d_out, int out_size)
{
    (void)in_sizes; (void)n_in; (void)out_size;
    const float* x     = (const float*)d_in[0];  // (N, T, D)
    const float* A     = (const float*)d_in[1];  // (N, H, 4, 4)
    const float* Wx    = (const float*)d_in[2];  // (D, 4H)
    const float* Wh    = (const float*)d_in[3];  // (H, 4H)
    const float* Wattn = (const float*)d_in[4];  // (H, 4H)
    const float* b     = (const float*)d_in[5];  // (4H,)
    float* out = (float*)d_out;                  // (N, T, H)

    init_kernel<<<Nn, 256>>>(A);

    dim3 gemm_grid(G4 / BN, Nn / BM);  // (64, 2)
    for (int t = 0; t < Tt; t++) {
        gemm_step_kernel<<<gemm_grid, 256>>>(x, Wh, Wattn, Wx, b, t);
        lstm_attn_kernel<<<Nn, 256>>>(A, out, t);
    }
}

// round 6
// speedup vs baseline: 3.3340x; 3.3340x over previous
#include <cuda_runtime.h>
#include <cuda_bf16.h>
#include <cstdint>
#include <cstddef>

// Problem dims
#define Nn 256
#define Tt 128
#define Dd 512
#define Hh 1024
#define G4 4096            // 4*H
#define Ktot 2560          // H (h) + H (attn) + D (x_t)

// ---------------- scratch (device globals: allocation-free rule) ----------------
__device__ float g_c[Nn * Hh];                         // LSTM cell state (fp32)
__device__ float g_gates[(size_t)Nn * G4];             // GEMM output (fp32)
__device__ __nv_bfloat16 g_Ahi[(size_t)Nn * 2048];     // [h | attn] hi
__device__ __nv_bfloat16 g_Alo[(size_t)Nn * 2048];     // [h | attn] lo
__device__ __nv_bfloat16 g_xhi[(size_t)Nn * Tt * Dd];  // x hi (all timesteps)
__device__ __nv_bfloat16 g_xlo[(size_t)Nn * Tt * Dd];  // x lo
__device__ __nv_bfloat16 g_WThi[(size_t)G4 * Ktot];    // W^T hi: [n][k], K-major
__device__ __nv_bfloat16 g_WTlo[(size_t)G4 * Ktot];    // W^T lo

// ---------------- PTX helpers (sm_80+ baseline features only) ----------------
__device__ __forceinline__ uint32_t smem_to_u32(const void* p) {
    uint32_t a;
    asm("{ .reg .u64 t; cvta.to.shared.u64 t, %1; cvt.u32.u64 %0, t; }" : "=r"(a) : "l"(p));
    return a;
}
#define CP_ASYNC16(dst, src) \
    asm volatile("cp.async.cg.shared.global [%0], [%1], 16;" :: "r"(dst), "l"(src))
#define CP_COMMIT() asm volatile("cp.async.commit_group;" ::: "memory")
#define CP_WAIT1()  asm volatile("cp.async.wait_group 1;" ::: "memory")
#define CP_WAIT0()  asm volatile("cp.async.wait_group 0;" ::: "memory")
#define LDSM_X4(r0, r1, r2, r3, addr)                                             \
    asm volatile("ldmatrix.sync.aligned.m8n8.x4.shared.b16 {%0,%1,%2,%3}, [%4];"  \
        : "=r"(r0), "=r"(r1), "=r"(r2), "=r"(r3) : "r"(addr))

__device__ __forceinline__ void mma16816(float* c, const uint32_t* a,
                                         uint32_t b0, uint32_t b1) {
    asm volatile(
        "mma.sync.aligned.m16n8k16.row.col.f32.bf16.bf16.f32 "
        "{%0,%1,%2,%3}, {%4,%5,%6,%7}, {%8,%9}, {%0,%1,%2,%3};"
        : "+f"(c[0]), "+f"(c[1]), "+f"(c[2]), "+f"(c[3])
        : "r"(a[0]), "r"(a[1]), "r"(a[2]), "r"(a[3]), "r"(b0), "r"(b1));
}

// ---------------- math helpers ----------------
__device__ __forceinline__ float sigmoidf_(float x) { return 1.0f / (1.0f + __expf(-x)); }
__device__ __forceinline__ float tanhf_(float x) {
    float e = __expf(2.0f * x);
    return 1.0f - 2.0f / (e + 1.0f);
}
__device__ __forceinline__ void split_bf16(float v, __nv_bfloat16& hi, __nv_bfloat16& lo) {
    hi = __float2bfloat16(v);
    lo = __float2bfloat16(v - __bfloat162float(hi));
}

// =====================================================================
// One-time: W^T hi/lo. WT[n][k] = bf16split(W[k][n]); K rows: Wh|Wattn|Wx
// =====================================================================
__global__ __launch_bounds__(256) void wconv_kernel(const float* __restrict__ Wx,
                                                    const float* __restrict__ Wh,
                                                    const float* __restrict__ Wattn)
{
    __shared__ float tile[32][33];
    const int nt = blockIdx.x * 32;
    const int kt = blockIdx.y * 32;
    const int tx = threadIdx.x & 31, ty = threadIdx.x >> 5;
#pragma unroll
    for (int r = 0; r < 4; r++) {
        int k = kt + ty + r * 8;
        int n = nt + tx;
        const float* src;
        if (k < 1024)       src = Wh    + (size_t)k * G4;
        else if (k < 2048)  src = Wattn + (size_t)(k - 1024) * G4;
        else                src = Wx    + (size_t)(k - 2048) * G4;
        tile[ty + r * 8][tx] = src[n];
    }
    __syncthreads();
#pragma unroll
    for (int r = 0; r < 4; r++) {
        int n = nt + ty + r * 8;
        int k = kt + tx;
        float v = tile[tx][ty + r * 8];
        __nv_bfloat16 hi, lo;
        split_bf16(v, hi, lo);
        g_WThi[(size_t)n * Ktot + k] = hi;
        g_WTlo[(size_t)n * Ktot + k] = lo;
    }
}

// One-time: x -> bf16 hi/lo
__global__ __launch_bounds__(256) void xconv_kernel(const float* __restrict__ x)
{
    const size_t total = (size_t)Nn * Tt * Dd;
    for (size_t i = (size_t)blockIdx.x * blockDim.x + threadIdx.x; i < total;
         i += (size_t)gridDim.x * blockDim.x) {
        __nv_bfloat16 hi, lo;
        split_bf16(x[i], hi, lo);
        g_xhi[i] = hi;
        g_xlo[i] = lo;
    }
}

// =====================================================================
// HMMA GEMM: gates = [h|attn|x_t] @ [Wh;Wattn;Wx] + b via bf16 hi/lo split.
// Per K-chunk (BK=32): load A_hi, A_lo, B_hi, B_lo once, issue 3 products:
//   A_hi*W_hi + A_hi*W_lo + A_lo*W_hi  (drop lo*lo, ~2^-18)
// BM=128, BN=64, 8 warps in 4x2 grid of 32x32 warp tiles, m16n8k16 mma.sync.
// Grid (64, 2) = 128 CTAs, 256 threads. Double-buffered cp.async pipeline.
// =====================================================================
#define GBM 128
#define GBN 64
#define GBK 32
#define NCH 80              // 2560 / 32
#define RSTR 80             // smem row stride bytes (32 bf16 + 8 pad = 40 elems)
// byte offsets inside dynamic smem (per-region, double buffered)
#define AH_OFF(buf) ((buf) * 10240)            // 128 rows * 80B
#define AL_OFF(buf) (20480 + (buf) * 10240)
#define BH_OFF(buf) (40960 + (buf) * 5120)     // 64 rows * 80B
#define BL_OFF(buf) (51200 + (buf) * 5120)
#define SMEM_DYN 61440

__global__ __launch_bounds__(256) void gemm_step_kernel(const float* __restrict__ b, int t)
{
    extern __shared__ __align__(128) __nv_bfloat16 dsm[];
    const uint32_t s0 = smem_to_u32(dsm);
    const int tid = threadIdx.x;
    const int lane = tid & 31;
    const int w = tid >> 5;
    const int wm = w & 3;        // 4 warps along M
    const int wn = w >> 2;       // 2 warps along N
    const int bn = blockIdx.x * GBN;
    const int bm = blockIdx.y * GBM;

    // loader mapping: row segments of 16B
    const int a_row = tid >> 2, a_seg = tid & 3;   // A: rows a_row and a_row+64
    const int b_row = tid >> 2, b_seg = tid & 3;   // B: rows 0..63

    // ldmatrix lane->address mapping
    // A m16k16 frag: lanes 0-15 rows 0-15 @ col-byte 0; lanes 16-31 rows 0-15 @ col-byte 16
    const uint32_t aOff = (uint32_t)((wm * 32 + (lane & 15)) * RSTR + (lane >> 4) * 16);
    // B (n-major [n][k]) frags: lanes 0-7 n0-7 k0; 8-15 n0-7 k16B; 16-23 n8-15 k0; 24-31 n8-15 k16B
    const int brow = (lane & 7) + ((lane >> 4) << 3);
    const uint32_t bOff = (uint32_t)((wn * 32 + brow) * RSTR + ((lane >> 3) & 1) * 16);

    auto issue = [&](int c, int buf) {
        const int kc = c * GBK;
        // B hi/lo
        {
            const size_t o = (size_t)(bn + b_row) * Ktot + kc + b_seg * 8;
            CP_ASYNC16(s0 + BH_OFF(buf) + b_row * RSTR + b_seg * 16, g_WThi + o);
            CP_ASYNC16(s0 + BL_OFF(buf) + b_row * RSTR + b_seg * 16, g_WTlo + o);
        }
        // A hi/lo (2 rows per thread)
#pragma unroll
        for (int r = 0; r < 2; r++) {
            const int m = a_row + r * 64;
            const __nv_bfloat16 *sh, *sl;
            if (kc < 2048) {
                const size_t o = (size_t)(bm + m) * 2048 + kc + a_seg * 8;
                sh = g_Ahi + o; sl = g_Alo + o;
            } else {
                const size_t o = (size_t)(bm + m) * (Tt * Dd) + (size_t)t * Dd
                               + (kc - 2048) + a_seg * 8;
                sh = g_xhi + o; sl = g_xlo + o;
            }
            const uint32_t d = m * RSTR + a_seg * 16;
            CP_ASYNC16(s0 + AH_OFF(buf) + d, sh);
            CP_ASYNC16(s0 + AL_OFF(buf) + d, sl);
        }
    };

    float acc[2][4][4];
#pragma unroll
    for (int mf = 0; mf < 2; mf++)
#pragma unroll
        for (int nf = 0; nf < 4; nf++)
#pragma unroll
            for (int i = 0; i < 4; i++) acc[mf][nf][i] = 0.0f;

    issue(0, 0);
    CP_COMMIT();

    for (int it = 0; it < NCH; it++) {
        const int buf = it & 1;
        if (it + 1 < NCH) {
            issue(it + 1, buf ^ 1);
            CP_COMMIT();
            CP_WAIT1();
        } else {
            CP_WAIT0();
        }
        __syncthreads();

        const uint32_t ah = s0 + AH_OFF(buf) + aOff;
        const uint32_t al = s0 + AL_OFF(buf) + aOff;
        const uint32_t bh = s0 + BH_OFF(buf) + bOff;
        const uint32_t bl = s0 + BL_OFF(buf) + bOff;

#pragma unroll
        for (int ks = 0; ks < 2; ks++) {
            const uint32_t ko = ks * 32;   // 16 elems * 2B
            uint32_t ahf[2][4], alf[2][4];
            uint32_t bhf[2][4], blf[2][4];
            LDSM_X4(ahf[0][0], ahf[0][1], ahf[0][2], ahf[0][3], ah + ko);
            LDSM_X4(ahf[1][0], ahf[1][1], ahf[1][2], ahf[1][3], ah + 16 * RSTR + ko);
            LDSM_X4(bhf[0][0], bhf[0][1], bhf[0][2], bhf[0][3], bh + ko);
            LDSM_X4(bhf[1][0], bhf[1][1], bhf[1][2], bhf[1][3], bh + 16 * RSTR + ko);
            LDSM_X4(blf[0][0], blf[0][1], blf[0][2], blf[0][3], bl + ko);
            LDSM_X4(blf[1][0], blf[1][1], blf[1][2], blf[1][3], bl + 16 * RSTR + ko);
            LDSM_X4(alf[0][0], alf[0][1], alf[0][2], alf[0][3], al + ko);
            LDSM_X4(alf[1][0], alf[1][1], alf[1][2], alf[1][3], al + 16 * RSTR + ko);

#pragma unroll
            for (int mf = 0; mf < 2; mf++) {
#pragma unroll
                for (int nf = 0; nf < 4; nf++) {
                    const uint32_t b0 = bhf[nf >> 1][(nf & 1) * 2];
                    const uint32_t b1 = bhf[nf >> 1][(nf & 1) * 2 + 1];
                    // A_hi * W_hi
                    mma16816(acc[mf][nf], ahf[mf], b0, b1);
                    // A_lo * W_hi
                    mma16816(acc[mf][nf], alf[mf], b0, b1);
                    // A_hi * W_lo
                    mma16816(acc[mf][nf], ahf[mf],
                             blf[nf >> 1][(nf & 1) * 2], blf[nf >> 1][(nf & 1) * 2 + 1]);
                }
            }
        }
        __syncthreads();
    }

    // epilogue: C frag layout -> gates (+bias)
#pragma unroll
    for (int mf = 0; mf < 2; mf++) {
        const int row0 = bm + wm * 32 + mf * 16 + (lane >> 2);
#pragma unroll
        for (int nf = 0; nf < 4; nf++) {
            const int col = bn + wn * 32 + nf * 8 + (lane & 3) * 2;
            const float b0v = b[col], b1v = b[col + 1];
            float2 v0 = make_float2(acc[mf][nf][0] + b0v, acc[mf][nf][1] + b1v);
            float2 v1 = make_float2(acc[mf][nf][2] + b0v, acc[mf][nf][3] + b1v);
            *(float2*)&g_gates[(size_t)row0 * G4 + col] = v0;
            *(float2*)&g_gates[(size_t)(row0 + 8) * G4 + col] = v1;
        }
    }
}

// =====================================================================
// Attention over the 4x4 grid (fp32). Writes attn as bf16 hi/lo into g_A*.
// =====================================================================
__device__ __forceinline__ void attention_block(int n, const float* __restrict__ A,
                                                const float* hs,
                                                __nv_bfloat16* ahi_row,
                                                __nv_bfloat16* alo_row, int tid)
{
    __shared__ float red[16][8];
    __shared__ float wsm[16];

    const float* An = A + (size_t)n * Hh * 16;

    float sc[16];
#pragma unroll
    for (int l = 0; l < 16; l++) sc[l] = 0.0f;

#pragma unroll
    for (int r = 0; r < 4; r++) {
        int hh = tid + r * 256;
        float hv = hs[hh];
        const float4* ar = (const float4*)(An + (size_t)hh * 16);
        float4 a0 = ar[0], a1 = ar[1], a2 = ar[2], a3 = ar[3];
        sc[0]  += a0.x * hv; sc[1]  += a0.y * hv; sc[2]  += a0.z * hv; sc[3]  += a0.w * hv;
        sc[4]  += a1.x * hv; sc[5]  += a1.y * hv; sc[6]  += a1.z * hv; sc[7]  += a1.w * hv;
        sc[8]  += a2.x * hv; sc[9]  += a2.y * hv; sc[10] += a2.z * hv; sc[11] += a2.w * hv;
        sc[12] += a3.x * hv; sc[13] += a3.y * hv; sc[14] += a3.z * hv; sc[15] += a3.w * hv;
    }
#pragma unroll
    for (int l = 0; l < 16; l++) {
#pragma unroll
        for (int off = 16; off > 0; off >>= 1)
            sc[l] += __shfl_xor_sync(0xffffffffu, sc[l], off);
    }
    int warp = tid >> 5, lane = tid & 31;
    if (lane == 0) {
#pragma unroll
        for (int l = 0; l < 16; l++) red[l][warp] = sc[l];
    }
    __syncthreads();
    if (tid == 0) {
        float s[16];
        float mx = -1e30f;
#pragma unroll
        for (int l = 0; l < 16; l++) {
            float v = 0.0f;
#pragma unroll
            for (int w = 0; w < 8; w++) v += red[l][w];
            v *= 0.03125f;  // 1/sqrt(1024)
            s[l] = v;
            mx = fmaxf(mx, v);
        }
        float sum = 0.0f;
#pragma unroll
        for (int l = 0; l < 16; l++) { float e = __expf(s[l] - mx); s[l] = e; sum += e; }
        float inv = 1.0f / sum;
#pragma unroll
        for (int l = 0; l < 16; l++) wsm[l] = s[l] * inv;
    }
    __syncthreads();

    float4 w0 = *(float4*)&wsm[0],  w1 = *(float4*)&wsm[4];
    float4 w2 = *(float4*)&wsm[8],  w3 = *(float4*)&wsm[12];
#pragma unroll
    for (int r = 0; r < 4; r++) {
        int hh = tid + r * 256;
        const float4* ar = (const float4*)(An + (size_t)hh * 16);
        float4 a0 = ar[0], a1 = ar[1], a2 = ar[2], a3 = ar[3];
        float v = a0.x * w0.x + a0.y * w0.y + a0.z * w0.z + a0.w * w0.w
                + a1.x * w1.x + a1.y * w1.y + a1.z * w1.z + a1.w * w1.w
                + a2.x * w2.x + a2.y * w2.y + a2.z * w2.z + a2.w * w2.w
                + a3.x * w3.x + a3.y * w3.y + a3.z * w3.z + a3.w * w3.w;
        __nv_bfloat16 hi, lo;
        split_bf16(v, hi, lo);
        ahi_row[1024 + hh] = hi;
        alo_row[1024 + hh] = lo;
    }
}

// =====================================================================
// Init: h0 = mean_l A[n,h,l]; c0 = h0; emit bf16 h0, then attention for step 0.
// =====================================================================
__global__ __launch_bounds__(256) void init_kernel(const float* __restrict__ A)
{
    __shared__ float hs[Hh];
    int n = blockIdx.x;
    int tid = threadIdx.x;
    const float* An = A + (size_t)n * Hh * 16;
    __nv_bfloat16* ahi = g_Ahi + (size_t)n * 2048;
    __nv_bfloat16* alo = g_Alo + (size_t)n * 2048;

#pragma unroll
    for (int r = 0; r < 4; r++) {
        int hh = tid + r * 256;
        const float4* ar = (const float4*)(An + (size_t)hh * 16);
        float4 a0 = ar[0], a1 = ar[1], a2 = ar[2], a3 = ar[3];
        float s = a0.x + a0.y + a0.z + a0.w + a1.x + a1.y + a1.z + a1.w
                + a2.x + a2.y + a2.z + a2.w + a3.x + a3.y + a3.z + a3.w;
        s *= (1.0f / 16.0f);
        g_c[(size_t)n * Hh + hh] = s;
        __nv_bfloat16 hi, lo;
        split_bf16(s, hi, lo);
        ahi[hh] = hi;
        alo[hh] = lo;
        hs[hh] = s;
    }
    __syncthreads();
    attention_block(n, A, hs, ahi, alo, tid);
}

// =====================================================================
// LSTM pointwise + next-step attention. Emits h/attn as bf16 hi/lo.
// =====================================================================
__global__ __launch_bounds__(256) void lstm_attn_kernel(const float* __restrict__ A,
                                                        float* __restrict__ out, int t)
{
    __shared__ float hs[Hh];
    int n = blockIdx.x;
    int tid = threadIdx.x;
    const float* gn = g_gates + (size_t)n * G4;
    __nv_bfloat16* ahi = g_Ahi + (size_t)n * 2048;
    __nv_bfloat16* alo = g_Alo + (size_t)n * 2048;

#pragma unroll
    for (int r = 0; r < 4; r++) {
        int hh = tid + r * 256;
        float iv = gn[hh];
        float fv = gn[Hh + hh];
        float ov = gn[2 * Hh + hh];
        float gv = gn[3 * Hh + hh];
        float c = g_c[(size_t)n * Hh + hh];
        float cn = sigmoidf_(fv) * c + sigmoidf_(iv) * tanhf_(gv);
        float hn = sigmoidf_(ov) * tanhf_(cn);
        g_c[(size_t)n * Hh + hh] = cn;
        out[(size_t)n * Tt * Hh + (size_t)t * Hh + hh] = hn;
        __nv_bfloat16 hi, lo;
        split_bf16(hn, hi, lo);
        ahi[hh] = hi;
        alo[hh] = lo;
        hs[hh] = hn;
    }
    __syncthreads();
    attention_block(n, A, hs, ahi, alo, tid);
}

// =====================================================================
// launch
// =====================================================================
extern "C" void kernel_launch(void* const* d_in, const int* in_sizes, int n_in,
                              void* d_out, int out_size)
{
    (void)in_sizes; (void)n_in; (void)out_size;
    const float* x     = (const float*)d_in[0];  // (N, T, D)
    const float* A     = (const float*)d_in[1];  // (N, H, 4, 4)
    const float* Wx    = (const float*)d_in[2];  // (D, 4H)
    const float* Wh    = (const float*)d_in[3];  // (H, 4H)
    const float* Wattn = (const float*)d_in[4];  // (H, 4H)
    const float* b     = (const float*)d_in[5];  // (4H,)
    float* out = (float*)d_out;                  // (N, T, H)

    static bool attr_set = false;
    if (!attr_set) {
        cudaFuncSetAttribute(gemm_step_kernel,
                             cudaFuncAttributeMaxDynamicSharedMemorySize, SMEM_DYN);
        attr_set = true;
    }

    // one-time conversions (inside the timed region; small)
    dim3 wgrid(G4 / 32, Ktot / 32);
    wconv_kernel<<<wgrid, 256>>>(Wx, Wh, Wattn);
    xconv_kernel<<<8192, 256>>>(x);
    init_kernel<<<Nn, 256>>>(A);

    dim3 gemm_grid(G4 / GBN, Nn / GBM);  // (64, 2) = 128 CTAs
    for (int t = 0; t < Tt; t++) {
        gemm_step_kernel<<<gemm_grid, 256, SMEM_DYN>>>(b, t);
        lstm_attn_kernel<<<Nn, 256>>>(A, out, t);
    }
}

// round 7
// speedup vs baseline: 3.8060x; 1.1416x over previous
#include <cuda_runtime.h>
#include <cuda_bf16.h>
#include <cstdint>
#include <cstddef>

// Problem dims
#define Nn 256
#define Tt 128
#define Dd 512
#define Hh 1024
#define G4 4096            // 4*H
#define Ktot 2560          // H (h) + H (attn) + D (x_t)

// ---------------- scratch (device globals: allocation-free rule) ----------------
__device__ float g_c[Nn * Hh];                         // LSTM cell state (fp32)
__device__ float g_gates0[(size_t)Nn * G4];            // GEMM partial (K half 0)
__device__ float g_gates1[(size_t)Nn * G4];            // GEMM partial (K half 1)
__device__ __nv_bfloat16 g_Ahi[(size_t)Nn * 2048];     // [h | attn] hi
__device__ __nv_bfloat16 g_Alo[(size_t)Nn * 2048];     // [h | attn] lo
__device__ __nv_bfloat16 g_xhi[(size_t)Nn * Tt * Dd];  // x hi (all timesteps)
__device__ __nv_bfloat16 g_xlo[(size_t)Nn * Tt * Dd];  // x lo
__device__ __nv_bfloat16 g_WThi[(size_t)G4 * Ktot];    // W^T hi: [n][k], K-major
__device__ __nv_bfloat16 g_WTlo[(size_t)G4 * Ktot];    // W^T lo

// ---------------- PTX helpers (sm_80+ baseline features only) ----------------
__device__ __forceinline__ uint32_t smem_to_u32(const void* p) {
    uint32_t a;
    asm("{ .reg .u64 t; cvta.to.shared.u64 t, %1; cvt.u32.u64 %0, t; }" : "=r"(a) : "l"(p));
    return a;
}
#define CP_ASYNC16(dst, src) \
    asm volatile("cp.async.cg.shared.global [%0], [%1], 16;" :: "r"(dst), "l"(src))
#define CP_COMMIT() asm volatile("cp.async.commit_group;" ::: "memory")
#define CP_WAIT1()  asm volatile("cp.async.wait_group 1;" ::: "memory")
#define CP_WAIT0()  asm volatile("cp.async.wait_group 0;" ::: "memory")
#define LDSM_X4(r0, r1, r2, r3, addr)                                             \
    asm volatile("ldmatrix.sync.aligned.m8n8.x4.shared.b16 {%0,%1,%2,%3}, [%4];"  \
        : "=r"(r0), "=r"(r1), "=r"(r2), "=r"(r3) : "r"(addr))

__device__ __forceinline__ void mma16816(float* c, const uint32_t* a,
                                         uint32_t b0, uint32_t b1) {
    asm volatile(
        "mma.sync.aligned.m16n8k16.row.col.f32.bf16.bf16.f32 "
        "{%0,%1,%2,%3}, {%4,%5,%6,%7}, {%8,%9}, {%0,%1,%2,%3};"
        : "+f"(c[0]), "+f"(c[1]), "+f"(c[2]), "+f"(c[3])
        : "r"(a[0]), "r"(a[1]), "r"(a[2]), "r"(a[3]), "r"(b0), "r"(b1));
}

// ---------------- math helpers ----------------
__device__ __forceinline__ float sigmoidf_(float x) { return 1.0f / (1.0f + __expf(-x)); }
__device__ __forceinline__ float tanhf_(float x) {
    float e = __expf(2.0f * x);
    return 1.0f - 2.0f / (e + 1.0f);
}
__device__ __forceinline__ void split_bf16(float v, __nv_bfloat16& hi, __nv_bfloat16& lo) {
    hi = __float2bfloat16(v);
    lo = __float2bfloat16(v - __bfloat162float(hi));
}

// =====================================================================
// One-time: W^T hi/lo. WT[n][k] = bf16split(W[k][n]); K rows: Wh|Wattn|Wx
// =====================================================================
__global__ __launch_bounds__(256) void wconv_kernel(const float* __restrict__ Wx,
                                                    const float* __restrict__ Wh,
                                                    const float* __restrict__ Wattn)
{
    __shared__ float tile[32][33];
    const int nt = blockIdx.x * 32;
    const int kt = blockIdx.y * 32;
    const int tx = threadIdx.x & 31, ty = threadIdx.x >> 5;
#pragma unroll
    for (int r = 0; r < 4; r++) {
        int k = kt + ty + r * 8;
        int n = nt + tx;
        const float* src;
        if (k < 1024)       src = Wh    + (size_t)k * G4;
        else if (k < 2048)  src = Wattn + (size_t)(k - 1024) * G4;
        else                src = Wx    + (size_t)(k - 2048) * G4;
        tile[ty + r * 8][tx] = src[n];
    }
    __syncthreads();
#pragma unroll
    for (int r = 0; r < 4; r++) {
        int n = nt + ty + r * 8;
        int k = kt + tx;
        float v = tile[tx][ty + r * 8];
        __nv_bfloat16 hi, lo;
        split_bf16(v, hi, lo);
        g_WThi[(size_t)n * Ktot + k] = hi;
        g_WTlo[(size_t)n * Ktot + k] = lo;
    }
}

// One-time: x -> bf16 hi/lo
__global__ __launch_bounds__(256) void xconv_kernel(const float* __restrict__ x)
{
    const size_t total = (size_t)Nn * Tt * Dd;
    for (size_t i = (size_t)blockIdx.x * blockDim.x + threadIdx.x; i < total;
         i += (size_t)gridDim.x * blockDim.x) {
        __nv_bfloat16 hi, lo;
        split_bf16(x[i], hi, lo);
        g_xhi[i] = hi;
        g_xlo[i] = lo;
    }
}

// =====================================================================
// HMMA GEMM, K-split x2: gates_part[z] = [h|attn|x_t](:, Kz) @ W(Kz, :)
// bf16 hi/lo split: A_hi*W_hi + A_lo*W_hi + A_hi*W_lo  (drop lo*lo, ~2^-18)
// BM=128, BN=64, 8 warps (4x2 of 32x32 warp tiles), m16n8k16 mma.sync.
// Grid (64, 2, 2) = 256 CTAs -> 2 CTAs/SM. 3-stage cp.async pipeline,
// ONE __syncthreads per chunk iteration.
// =====================================================================
#define GBM 128
#define GBN 64
#define GBK 32
#define NCH 40               // (2560/2) / 32 per K half
#define KHALF 1280
#define RSTR 80              // smem row stride bytes (32 bf16 + 8 pad)
// per-stage region offsets (stage stride = 30720 B)
#define STG 30720
#define AH_OFF(s) ((s) * STG)
#define AL_OFF(s) ((s) * STG + 10240)
#define BH_OFF(s) ((s) * STG + 20480)
#define BL_OFF(s) ((s) * STG + 25600)
#define SMEM_DYN (3 * STG)   // 92160

__global__ __launch_bounds__(256) void gemm_step_kernel(int t)
{
    extern __shared__ __align__(128) __nv_bfloat16 dsm[];
    const uint32_t s0 = smem_to_u32(dsm);
    const int tid = threadIdx.x;
    const int lane = tid & 31;
    const int w = tid >> 5;
    const int wm = w & 3;        // 4 warps along M
    const int wn = w >> 2;       // 2 warps along N
    const int bn = blockIdx.x * GBN;
    const int bm = blockIdx.y * GBM;
    const int kz = blockIdx.z;               // K half
    const int kbase = kz * KHALF;

    // loader mapping: row segments of 16B
    const int a_row = tid >> 2, a_seg = tid & 3;   // A: rows a_row and a_row+64
    const int b_row = tid >> 2, b_seg = tid & 3;   // B: rows 0..63

    // ldmatrix lane->address mapping
    const uint32_t aOff = (uint32_t)((wm * 32 + (lane & 15)) * RSTR + (lane >> 4) * 16);
    const int brow = (lane & 7) + ((lane >> 4) << 3);
    const uint32_t bOff = (uint32_t)((wn * 32 + brow) * RSTR + ((lane >> 3) & 1) * 16);

    auto issue = [&](int c, int s) {
        const int kc = kbase + c * GBK;
        // B hi/lo
        {
            const size_t o = (size_t)(bn + b_row) * Ktot + kc + b_seg * 8;
            CP_ASYNC16(s0 + BH_OFF(s) + b_row * RSTR + b_seg * 16, g_WThi + o);
            CP_ASYNC16(s0 + BL_OFF(s) + b_row * RSTR + b_seg * 16, g_WTlo + o);
        }
        // A hi/lo (2 rows per thread)
#pragma unroll
        for (int r = 0; r < 2; r++) {
            const int m = a_row + r * 64;
            const __nv_bfloat16 *sh, *sl;
            if (kc < 2048) {
                const size_t o = (size_t)(bm + m) * 2048 + kc + a_seg * 8;
                sh = g_Ahi + o; sl = g_Alo + o;
            } else {
                const size_t o = (size_t)(bm + m) * (Tt * Dd) + (size_t)t * Dd
                               + (kc - 2048) + a_seg * 8;
                sh = g_xhi + o; sl = g_xlo + o;
            }
            const uint32_t d = m * RSTR + a_seg * 16;
            CP_ASYNC16(s0 + AH_OFF(s) + d, sh);
            CP_ASYNC16(s0 + AL_OFF(s) + d, sl);
        }
    };

    float acc[2][4][4];
#pragma unroll
    for (int mf = 0; mf < 2; mf++)
#pragma unroll
        for (int nf = 0; nf < 4; nf++)
#pragma unroll
            for (int i = 0; i < 4; i++) acc[mf][nf][i] = 0.0f;

    issue(0, 0); CP_COMMIT();
    issue(1, 1); CP_COMMIT();

    int stage = 0;
    for (int it = 0; it < NCH; it++) {
        if (it == NCH - 1) { CP_WAIT0(); } else { CP_WAIT1(); }
        __syncthreads();
        // prefetch chunk it+2 into the buffer freed by chunk it-1
        if (it + 2 < NCH) {
            int ns = stage + 2; if (ns >= 3) ns -= 3;
            issue(it + 2, ns);
            CP_COMMIT();
        }

        const uint32_t ah = s0 + AH_OFF(stage) + aOff;
        const uint32_t al = s0 + AL_OFF(stage) + aOff;
        const uint32_t bh = s0 + BH_OFF(stage) + bOff;
        const uint32_t bl = s0 + BL_OFF(stage) + bOff;

#pragma unroll
        for (int ks = 0; ks < 2; ks++) {
            const uint32_t ko = ks * 32;   // 16 elems * 2B
            uint32_t ahf[2][4], alf[2][4];
            uint32_t bhf[2][4], blf[2][4];
            LDSM_X4(ahf[0][0], ahf[0][1], ahf[0][2], ahf[0][3], ah + ko);
            LDSM_X4(ahf[1][0], ahf[1][1], ahf[1][2], ahf[1][3], ah + 16 * RSTR + ko);
            LDSM_X4(bhf[0][0], bhf[0][1], bhf[0][2], bhf[0][3], bh + ko);
            LDSM_X4(bhf[1][0], bhf[1][1], bhf[1][2], bhf[1][3], bh + 16 * RSTR + ko);
            LDSM_X4(blf[0][0], blf[0][1], blf[0][2], blf[0][3], bl + ko);
            LDSM_X4(blf[1][0], blf[1][1], blf[1][2], blf[1][3], bl + 16 * RSTR + ko);
            LDSM_X4(alf[0][0], alf[0][1], alf[0][2], alf[0][3], al + ko);
            LDSM_X4(alf[1][0], alf[1][1], alf[1][2], alf[1][3], al + 16 * RSTR + ko);

#pragma unroll
            for (int mf = 0; mf < 2; mf++) {
#pragma unroll
                for (int nf = 0; nf < 4; nf++) {
                    const uint32_t b0 = bhf[nf >> 1][(nf & 1) * 2];
                    const uint32_t b1 = bhf[nf >> 1][(nf & 1) * 2 + 1];
                    mma16816(acc[mf][nf], ahf[mf], b0, b1);           // hi*hi
                    mma16816(acc[mf][nf], alf[mf], b0, b1);           // lo*hi
                    mma16816(acc[mf][nf], ahf[mf],                    // hi*lo
                             blf[nf >> 1][(nf & 1) * 2], blf[nf >> 1][(nf & 1) * 2 + 1]);
                }
            }
        }
        stage = (stage + 1 == 3) ? 0 : stage + 1;
    }

    // epilogue: C frag layout -> partial gates buffer for this K half
    float* gpart = kz ? g_gates1 : g_gates0;
#pragma unroll
    for (int mf = 0; mf < 2; mf++) {
        const int row0 = bm + wm * 32 + mf * 16 + (lane >> 2);
#pragma unroll
        for (int nf = 0; nf < 4; nf++) {
            const int col = bn + wn * 32 + nf * 8 + (lane & 3) * 2;
            float2 v0 = make_float2(acc[mf][nf][0], acc[mf][nf][1]);
            float2 v1 = make_float2(acc[mf][nf][2], acc[mf][nf][3]);
            *(float2*)&gpart[(size_t)row0 * G4 + col] = v0;
            *(float2*)&gpart[(size_t)(row0 + 8) * G4 + col] = v1;
        }
    }
}

// =====================================================================
// Attention over the 4x4 grid (fp32). Writes attn as bf16 hi/lo into g_A*.
// =====================================================================
__device__ __forceinline__ void attention_block(int n, const float* __restrict__ A,
                                                const float* hs,
                                                __nv_bfloat16* ahi_row,
                                                __nv_bfloat16* alo_row, int tid)
{
    __shared__ float red[16][8];
    __shared__ float wsm[16];

    const float* An = A + (size_t)n * Hh * 16;

    float sc[16];
#pragma unroll
    for (int l = 0; l < 16; l++) sc[l] = 0.0f;

#pragma unroll
    for (int r = 0; r < 4; r++) {
        int hh = tid + r * 256;
        float hv = hs[hh];
        const float4* ar = (const float4*)(An + (size_t)hh * 16);
        float4 a0 = ar[0], a1 = ar[1], a2 = ar[2], a3 = ar[3];
        sc[0]  += a0.x * hv; sc[1]  += a0.y * hv; sc[2]  += a0.z * hv; sc[3]  += a0.w * hv;
        sc[4]  += a1.x * hv; sc[5]  += a1.y * hv; sc[6]  += a1.z * hv; sc[7]  += a1.w * hv;
        sc[8]  += a2.x * hv; sc[9]  += a2.y * hv; sc[10] += a2.z * hv; sc[11] += a2.w * hv;
        sc[12] += a3.x * hv; sc[13] += a3.y * hv; sc[14] += a3.z * hv; sc[15] += a3.w * hv;
    }
#pragma unroll
    for (int l = 0; l < 16; l++) {
#pragma unroll
        for (int off = 16; off > 0; off >>= 1)
            sc[l] += __shfl_xor_sync(0xffffffffu, sc[l], off);
    }
    int warp = tid >> 5, lane = tid & 31;
    if (lane == 0) {
#pragma unroll
        for (int l = 0; l < 16; l++) red[l][warp] = sc[l];
    }
    __syncthreads();
    if (tid == 0) {
        float s[16];
        float mx = -1e30f;
#pragma unroll
        for (int l = 0; l < 16; l++) {
            float v = 0.0f;
#pragma unroll
            for (int w = 0; w < 8; w++) v += red[l][w];
            v *= 0.03125f;  // 1/sqrt(1024)
            s[l] = v;
            mx = fmaxf(mx, v);
        }
        float sum = 0.0f;
#pragma unroll
        for (int l = 0; l < 16; l++) { float e = __expf(s[l] - mx); s[l] = e; sum += e; }
        float inv = 1.0f / sum;
#pragma unroll
        for (int l = 0; l < 16; l++) wsm[l] = s[l] * inv;
    }
    __syncthreads();

    float4 w0 = *(float4*)&wsm[0],  w1 = *(float4*)&wsm[4];
    float4 w2 = *(float4*)&wsm[8],  w3 = *(float4*)&wsm[12];
#pragma unroll
    for (int r = 0; r < 4; r++) {
        int hh = tid + r * 256;
        const float4* ar = (const float4*)(An + (size_t)hh * 16);
        float4 a0 = ar[0], a1 = ar[1], a2 = ar[2], a3 = ar[3];
        float v = a0.x * w0.x + a0.y * w0.y + a0.z * w0.z + a0.w * w0.w
                + a1.x * w1.x + a1.y * w1.y + a1.z * w1.z + a1.w * w1.w
                + a2.x * w2.x + a2.y * w2.y + a2.z * w2.z + a2.w * w2.w
                + a3.x * w3.x + a3.y * w3.y + a3.z * w3.z + a3.w * w3.w;
        __nv_bfloat16 hi, lo;
        split_bf16(v, hi, lo);
        ahi_row[1024 + hh] = hi;
        alo_row[1024 + hh] = lo;
    }
}

// =====================================================================
// Init: h0 = mean_l A[n,h,l]; c0 = h0; emit bf16 h0, then attention for step 0.
// =====================================================================
__global__ __launch_bounds__(256) void init_kernel(const float* __restrict__ A)
{
    __shared__ float hs[Hh];
    int n = blockIdx.x;
    int tid = threadIdx.x;
    const float* An = A + (size_t)n * Hh * 16;
    __nv_bfloat16* ahi = g_Ahi + (size_t)n * 2048;
    __nv_bfloat16* alo = g_Alo + (size_t)n * 2048;

#pragma unroll
    for (int r = 0; r < 4; r++) {
        int hh = tid + r * 256;
        const float4* ar = (const float4*)(An + (size_t)hh * 16);
        float4 a0 = ar[0], a1 = ar[1], a2 = ar[2], a3 = ar[3];
        float s = a0.x + a0.y + a0.z + a0.w + a1.x + a1.y + a1.z + a1.w
                + a2.x + a2.y + a2.z + a2.w + a3.x + a3.y + a3.z + a3.w;
        s *= (1.0f / 16.0f);
        g_c[(size_t)n * Hh + hh] = s;
        __nv_bfloat16 hi, lo;
        split_bf16(s, hi, lo);
        ahi[hh] = hi;
        alo[hh] = lo;
        hs[hh] = s;
    }
    __syncthreads();
    attention_block(n, A, hs, ahi, alo, tid);
}

// =====================================================================
// LSTM pointwise (+bias, +partial-sum reduce) + next-step attention.
// =====================================================================
__global__ __launch_bounds__(256) void lstm_attn_kernel(const float* __restrict__ A,
                                                        const float* __restrict__ b,
                                                        float* __restrict__ out, int t)
{
    __shared__ float hs[Hh];
    int n = blockIdx.x;
    int tid = threadIdx.x;
    const float* g0 = g_gates0 + (size_t)n * G4;
    const float* g1 = g_gates1 + (size_t)n * G4;
    __nv_bfloat16* ahi = g_Ahi + (size_t)n * 2048;
    __nv_bfloat16* alo = g_Alo + (size_t)n * 2048;

#pragma unroll
    for (int r = 0; r < 4; r++) {
        int hh = tid + r * 256;
        float iv = g0[hh]          + g1[hh]          + b[hh];
        float fv = g0[Hh + hh]     + g1[Hh + hh]     + b[Hh + hh];
        float ov = g0[2 * Hh + hh] + g1[2 * Hh + hh] + b[2 * Hh + hh];
        float gv = g0[3 * Hh + hh] + g1[3 * Hh + hh] + b[3 * Hh + hh];
        float c = g_c[(size_t)n * Hh + hh];
        float cn = sigmoidf_(fv) * c + sigmoidf_(iv) * tanhf_(gv);
        float hn = sigmoidf_(ov) * tanhf_(cn);
        g_c[(size_t)n * Hh + hh] = cn;
        out[(size_t)n * Tt * Hh + (size_t)t * Hh + hh] = hn;
        __nv_bfloat16 hi, lo;
        split_bf16(hn, hi, lo);
        ahi[hh] = hi;
        alo[hh] = lo;
        hs[hh] = hn;
    }
    __syncthreads();
    attention_block(n, A, hs, ahi, alo, tid);
}

// =====================================================================
// launch
// =====================================================================
extern "C" void kernel_launch(void* const* d_in, const int* in_sizes, int n_in,
                              void* d_out, int out_size)
{
    (void)in_sizes; (void)n_in; (void)out_size;
    const float* x     = (const float*)d_in[0];  // (N, T, D)
    const float* A     = (const float*)d_in[1];  // (N, H, 4, 4)
    const float* Wx    = (const float*)d_in[2];  // (D, 4H)
    const float* Wh    = (const float*)d_in[3];  // (H, 4H)
    const float* Wattn = (const float*)d_in[4];  // (H, 4H)
    const float* b     = (const float*)d_in[5];  // (4H,)
    float* out = (float*)d_out;                  // (N, T, H)

    cudaFuncSetAttribute(gemm_step_kernel,
                         cudaFuncAttributeMaxDynamicSharedMemorySize, SMEM_DYN);

    // one-time conversions (inside the timed region; small)
    dim3 wgrid(G4 / 32, Ktot / 32);
    wconv_kernel<<<wgrid, 256>>>(Wx, Wh, Wattn);
    xconv_kernel<<<8192, 256>>>(x);
    init_kernel<<<Nn, 256>>>(A);

    dim3 gemm_grid(G4 / GBN, Nn / GBM, 2);  // (64, 2, 2) = 256 CTAs
    for (int t = 0; t < Tt; t++) {
        gemm_step_kernel<<<gemm_grid, 256, SMEM_DYN>>>(t);
        lstm_attn_kernel<<<Nn, 256>>>(A, b, out, t);
    }
}

// round 8
// speedup vs baseline: 3.9669x; 1.0423x over previous
#include <cuda_runtime.h>
#include <cuda_bf16.h>
#include <cstdint>
#include <cstddef>

// Problem dims
#define Nn 256
#define Tt 128
#define Dd 512
#define Hh 1024
#define G4 4096            // 4*H
#define Ktot 2560          // H (h) + H (attn) + D (x_t) in W layout
#define Krec 2048          // recurrent K (h | attn) per step

// ---------------- scratch (device globals: allocation-free rule) ----------------
__device__ float g_c[Nn * Hh];                          // LSTM cell state (fp32)
__device__ float g_gp[(size_t)4 * Nn * G4];             // GEMM partials (4 K-splits)
__device__ float g_xw[(size_t)Tt * Nn * G4];            // precomputed x@Wx, [t][n][4H]
__device__ __nv_bfloat16 g_Ahi[(size_t)Nn * 2048];      // [h | attn] hi
__device__ __nv_bfloat16 g_Alo[(size_t)Nn * 2048];      // [h | attn] lo
__device__ __nv_bfloat16 g_xhi[(size_t)Nn * Tt * Dd];   // x hi
__device__ __nv_bfloat16 g_xlo[(size_t)Nn * Tt * Dd];   // x lo
__device__ __nv_bfloat16 g_WThi[(size_t)G4 * Ktot];     // W^T hi: [n][k], K-major
__device__ __nv_bfloat16 g_WTlo[(size_t)G4 * Ktot];     // W^T lo

// ---------------- PTX helpers (sm_80+ baseline features only) ----------------
__device__ __forceinline__ uint32_t smem_to_u32(const void* p) {
    uint32_t a;
    asm("{ .reg .u64 t; cvta.to.shared.u64 t, %1; cvt.u32.u64 %0, t; }" : "=r"(a) : "l"(p));
    return a;
}
#define CP_ASYNC16(dst, src) \
    asm volatile("cp.async.cg.shared.global [%0], [%1], 16;" :: "r"(dst), "l"(src))
#define CP_COMMIT() asm volatile("cp.async.commit_group;" ::: "memory")
#define CP_WAIT0()  asm volatile("cp.async.wait_group 0;" ::: "memory")
#define LDSM_X4(r0, r1, r2, r3, addr)                                             \
    asm volatile("ldmatrix.sync.aligned.m8n8.x4.shared.b16 {%0,%1,%2,%3}, [%4];"  \
        : "=r"(r0), "=r"(r1), "=r"(r2), "=r"(r3) : "r"(addr))

__device__ __forceinline__ void mma16816(float* c, const uint32_t* a,
                                         uint32_t b0, uint32_t b1) {
    asm volatile(
        "mma.sync.aligned.m16n8k16.row.col.f32.bf16.bf16.f32 "
        "{%0,%1,%2,%3}, {%4,%5,%6,%7}, {%8,%9}, {%0,%1,%2,%3};"
        : "+f"(c[0]), "+f"(c[1]), "+f"(c[2]), "+f"(c[3])
        : "r"(a[0]), "r"(a[1]), "r"(a[2]), "r"(a[3]), "r"(b0), "r"(b1));
}

// ---------------- math helpers ----------------
__device__ __forceinline__ float sigmoidf_(float x) { return 1.0f / (1.0f + __expf(-x)); }
__device__ __forceinline__ float tanhf_(float x) {
    float e = __expf(2.0f * x);
    return 1.0f - 2.0f / (e + 1.0f);
}
__device__ __forceinline__ void split_bf16(float v, __nv_bfloat16& hi, __nv_bfloat16& lo) {
    hi = __float2bfloat16(v);
    lo = __float2bfloat16(v - __bfloat162float(hi));
}

// ---------------- shared GEMM tiling ----------------
#define GBM 128
#define GBN 64
#define GBK 32
#define RSTR 80              // smem row stride bytes (32 bf16 + 8 pad)
#define STG 30720            // bytes per pipeline stage
#define AH_OFF(s) ((s) * STG)
#define AL_OFF(s) ((s) * STG + 10240)
#define BH_OFF(s) ((s) * STG + 20480)
#define BL_OFF(s) ((s) * STG + 25600)
#define SMEM_DYN (2 * STG)   // 61440 -> 3 CTAs/SM

// Fragment compute for one chunk stage (shared by both GEMM kernels).
// acc[2][4][4]; aOff/bOff are per-lane ldmatrix offsets.
__device__ __forceinline__ void compute_chunk(uint32_t s0, int stage,
                                              uint32_t aOff, uint32_t bOff,
                                              float acc[2][4][4])
{
    const uint32_t ah = s0 + AH_OFF(stage) + aOff;
    const uint32_t al = s0 + AL_OFF(stage) + aOff;
    const uint32_t bh = s0 + BH_OFF(stage) + bOff;
    const uint32_t bl = s0 + BL_OFF(stage) + bOff;
#pragma unroll
    for (int ks = 0; ks < 2; ks++) {
        const uint32_t ko = ks * 32;   // 16 elems * 2B
        uint32_t ahf[2][4], alf[2][4];
        uint32_t bhf[2][4], blf[2][4];
        LDSM_X4(ahf[0][0], ahf[0][1], ahf[0][2], ahf[0][3], ah + ko);
        LDSM_X4(ahf[1][0], ahf[1][1], ahf[1][2], ahf[1][3], ah + 16 * RSTR + ko);
        LDSM_X4(bhf[0][0], bhf[0][1], bhf[0][2], bhf[0][3], bh + ko);
        LDSM_X4(bhf[1][0], bhf[1][1], bhf[1][2], bhf[1][3], bh + 16 * RSTR + ko);
        LDSM_X4(blf[0][0], blf[0][1], blf[0][2], blf[0][3], bl + ko);
        LDSM_X4(blf[1][0], blf[1][1], blf[1][2], blf[1][3], bl + 16 * RSTR + ko);
        LDSM_X4(alf[0][0], alf[0][1], alf[0][2], alf[0][3], al + ko);
        LDSM_X4(alf[1][0], alf[1][1], alf[1][2], alf[1][3], al + 16 * RSTR + ko);
#pragma unroll
        for (int mf = 0; mf < 2; mf++) {
#pragma unroll
            for (int nf = 0; nf < 4; nf++) {
                const uint32_t b0 = bhf[nf >> 1][(nf & 1) * 2];
                const uint32_t b1 = bhf[nf >> 1][(nf & 1) * 2 + 1];
                mma16816(acc[mf][nf], ahf[mf], b0, b1);           // hi*hi
                mma16816(acc[mf][nf], alf[mf], b0, b1);           // lo*hi
                mma16816(acc[mf][nf], ahf[mf],                    // hi*lo
                         blf[nf >> 1][(nf & 1) * 2], blf[nf >> 1][(nf & 1) * 2 + 1]);
            }
        }
    }
}

// =====================================================================
// One-time: W^T hi/lo. WT[n][k] = bf16split(W[k][n]); K rows: Wh|Wattn|Wx
// =====================================================================
__global__ __launch_bounds__(256) void wconv_kernel(const float* __restrict__ Wx,
                                                    const float* __restrict__ Wh,
                                                    const float* __restrict__ Wattn)
{
    __shared__ float tile[32][33];
    const int nt = blockIdx.x * 32;
    const int kt = blockIdx.y * 32;
    const int tx = threadIdx.x & 31, ty = threadIdx.x >> 5;
#pragma unroll
    for (int r = 0; r < 4; r++) {
        int k = kt + ty + r * 8;
        int n = nt + tx;
        const float* src;
        if (k < 1024)       src = Wh    + (size_t)k * G4;
        else if (k < 2048)  src = Wattn + (size_t)(k - 1024) * G4;
        else                src = Wx    + (size_t)(k - 2048) * G4;
        tile[ty + r * 8][tx] = src[n];
    }
    __syncthreads();
#pragma unroll
    for (int r = 0; r < 4; r++) {
        int n = nt + ty + r * 8;
        int k = kt + tx;
        float v = tile[tx][ty + r * 8];
        __nv_bfloat16 hi, lo;
        split_bf16(v, hi, lo);
        g_WThi[(size_t)n * Ktot + k] = hi;
        g_WTlo[(size_t)n * Ktot + k] = lo;
    }
}

// One-time: x -> bf16 hi/lo
__global__ __launch_bounds__(256) void xconv_kernel(const float* __restrict__ x)
{
    const size_t total = (size_t)Nn * Tt * Dd;
    for (size_t i = (size_t)blockIdx.x * blockDim.x + threadIdx.x; i < total;
         i += (size_t)gridDim.x * blockDim.x) {
        __nv_bfloat16 hi, lo;
        split_bf16(x[i], hi, lo);
        g_xhi[i] = hi;
        g_xlo[i] = lo;
    }
}

// =====================================================================
// One-time big GEMM: xw[t][n][:] = x[n][t][:] @ Wx + 0   (bf16 hi/lo x3)
// M = N*T = 32768 (row m = n*128 + t, contiguous in x), K = 512, N = 4096.
// Grid (64, 256) = 16384 CTAs.
// =====================================================================
__global__ __launch_bounds__(256, 3) void gemm_xw_kernel()
{
    extern __shared__ __align__(128) __nv_bfloat16 dsm[];
    const uint32_t s0 = smem_to_u32(dsm);
    const int tid = threadIdx.x;
    const int lane = tid & 31;
    const int w = tid >> 5;
    const int wm = w & 3, wn = w >> 2;
    const int bn = blockIdx.x * GBN;
    const int bm = blockIdx.y * GBM;

    const int a_row = tid >> 2, a_seg = tid & 3;
    const int b_row = tid >> 2, b_seg = tid & 3;
    const uint32_t aOff = (uint32_t)((wm * 32 + (lane & 15)) * RSTR + (lane >> 4) * 16);
    const int brow = (lane & 7) + ((lane >> 4) << 3);
    const uint32_t bOff = (uint32_t)((wn * 32 + brow) * RSTR + ((lane >> 3) & 1) * 16);

    auto issue = [&](int c, int s) {
        const int kc = c * GBK;
        {
            const size_t o = (size_t)(bn + b_row) * Ktot + 2048 + kc + b_seg * 8;
            CP_ASYNC16(s0 + BH_OFF(s) + b_row * RSTR + b_seg * 16, g_WThi + o);
            CP_ASYNC16(s0 + BL_OFF(s) + b_row * RSTR + b_seg * 16, g_WTlo + o);
        }
#pragma unroll
        for (int r = 0; r < 2; r++) {
            const int m = a_row + r * 64;
            const size_t o = (size_t)(bm + m) * Dd + kc + a_seg * 8;
            const uint32_t d = m * RSTR + a_seg * 16;
            CP_ASYNC16(s0 + AH_OFF(s) + d, g_xhi + o);
            CP_ASYNC16(s0 + AL_OFF(s) + d, g_xlo + o);
        }
    };

    float acc[2][4][4];
#pragma unroll
    for (int mf = 0; mf < 2; mf++)
#pragma unroll
        for (int nf = 0; nf < 4; nf++)
#pragma unroll
            for (int i = 0; i < 4; i++) acc[mf][nf][i] = 0.0f;

    const int NCH = Dd / GBK;  // 16
    issue(0, 0); CP_COMMIT();
    for (int it = 0; it < NCH; it++) {
        CP_WAIT0();
        __syncthreads();
        if (it + 1 < NCH) { issue(it + 1, (it + 1) & 1); CP_COMMIT(); }
        compute_chunk(s0, it & 1, aOff, bOff, acc);
    }

    // epilogue: row m -> (n = m>>7, t = m&127); xw[t][n][col]
#pragma unroll
    for (int mf = 0; mf < 2; mf++) {
        const int m0 = bm + wm * 32 + mf * 16 + (lane >> 2);
#pragma unroll
        for (int pr = 0; pr < 2; pr++) {
            const int m = m0 + pr * 8;
            float* xrow = g_xw + ((size_t)(m & 127) * Nn + (m >> 7)) * G4;
#pragma unroll
            for (int nf = 0; nf < 4; nf++) {
                const int col = bn + wn * 32 + nf * 8 + (lane & 3) * 2;
                *(float2*)&xrow[col] =
                    make_float2(acc[mf][nf][pr * 2], acc[mf][nf][pr * 2 + 1]);
            }
        }
    }
}

// =====================================================================
// Per-step GEMM over recurrent K=2048, K-split x4.
// gp[kz] = [h|attn](:, Kz) @ W(Kz, :). Grid (64, 2, 4) = 512 CTAs.
// =====================================================================
#define NCHS 16              // (2048/4) / 32
#define KQ 512

__global__ __launch_bounds__(256, 3) void gemm_step_kernel(int t)
{
    (void)t;
    extern __shared__ __align__(128) __nv_bfloat16 dsm[];
    const uint32_t s0 = smem_to_u32(dsm);
    const int tid = threadIdx.x;
    const int lane = tid & 31;
    const int w = tid >> 5;
    const int wm = w & 3, wn = w >> 2;
    const int bn = blockIdx.x * GBN;
    const int bm = blockIdx.y * GBM;
    const int kz = blockIdx.z;
    const int kbase = kz * KQ;

    const int a_row = tid >> 2, a_seg = tid & 3;
    const int b_row = tid >> 2, b_seg = tid & 3;
    const uint32_t aOff = (uint32_t)((wm * 32 + (lane & 15)) * RSTR + (lane >> 4) * 16);
    const int brow = (lane & 7) + ((lane >> 4) << 3);
    const uint32_t bOff = (uint32_t)((wn * 32 + brow) * RSTR + ((lane >> 3) & 1) * 16);

    auto issue = [&](int c, int s) {
        const int kc = kbase + c * GBK;
        {
            const size_t o = (size_t)(bn + b_row) * Ktot + kc + b_seg * 8;
            CP_ASYNC16(s0 + BH_OFF(s) + b_row * RSTR + b_seg * 16, g_WThi + o);
            CP_ASYNC16(s0 + BL_OFF(s) + b_row * RSTR + b_seg * 16, g_WTlo + o);
        }
#pragma unroll
        for (int r = 0; r < 2; r++) {
            const int m = a_row + r * 64;
            const size_t o = (size_t)(bm + m) * Krec + kc + a_seg * 8;
            const uint32_t d = m * RSTR + a_seg * 16;
            CP_ASYNC16(s0 + AH_OFF(s) + d, g_Ahi + o);
            CP_ASYNC16(s0 + AL_OFF(s) + d, g_Alo + o);
        }
    };

    float acc[2][4][4];
#pragma unroll
    for (int mf = 0; mf < 2; mf++)
#pragma unroll
        for (int nf = 0; nf < 4; nf++)
#pragma unroll
            for (int i = 0; i < 4; i++) acc[mf][nf][i] = 0.0f;

    issue(0, 0); CP_COMMIT();
    for (int it = 0; it < NCHS; it++) {
        CP_WAIT0();
        __syncthreads();
        if (it + 1 < NCHS) { issue(it + 1, (it + 1) & 1); CP_COMMIT(); }
        compute_chunk(s0, it & 1, aOff, bOff, acc);
    }

    float* gpart = g_gp + (size_t)kz * Nn * G4;
#pragma unroll
    for (int mf = 0; mf < 2; mf++) {
        const int row0 = bm + wm * 32 + mf * 16 + (lane >> 2);
#pragma unroll
        for (int nf = 0; nf < 4; nf++) {
            const int col = bn + wn * 32 + nf * 8 + (lane & 3) * 2;
            *(float2*)&gpart[(size_t)row0 * G4 + col] =
                make_float2(acc[mf][nf][0], acc[mf][nf][1]);
            *(float2*)&gpart[(size_t)(row0 + 8) * G4 + col] =
                make_float2(acc[mf][nf][2], acc[mf][nf][3]);
        }
    }
}

// =====================================================================
// Attention over the 4x4 grid (fp32). Writes attn as bf16 hi/lo into g_A*.
// =====================================================================
__device__ __forceinline__ void attention_block(int n, const float* __restrict__ A,
                                                const float* hs,
                                                __nv_bfloat16* ahi_row,
                                                __nv_bfloat16* alo_row, int tid)
{
    __shared__ float red[16][8];
    __shared__ float wsm[16];

    const float* An = A + (size_t)n * Hh * 16;

    float sc[16];
#pragma unroll
    for (int l = 0; l < 16; l++) sc[l] = 0.0f;

#pragma unroll
    for (int r = 0; r < 4; r++) {
        int hh = tid + r * 256;
        float hv = hs[hh];
        const float4* ar = (const float4*)(An + (size_t)hh * 16);
        float4 a0 = ar[0], a1 = ar[1], a2 = ar[2], a3 = ar[3];
        sc[0]  += a0.x * hv; sc[1]  += a0.y * hv; sc[2]  += a0.z * hv; sc[3]  += a0.w * hv;
        sc[4]  += a1.x * hv; sc[5]  += a1.y * hv; sc[6]  += a1.z * hv; sc[7]  += a1.w * hv;
        sc[8]  += a2.x * hv; sc[9]  += a2.y * hv; sc[10] += a2.z * hv; sc[11] += a2.w * hv;
        sc[12] += a3.x * hv; sc[13] += a3.y * hv; sc[14] += a3.z * hv; sc[15] += a3.w * hv;
    }
#pragma unroll
    for (int l = 0; l < 16; l++) {
#pragma unroll
        for (int off = 16; off > 0; off >>= 1)
            sc[l] += __shfl_xor_sync(0xffffffffu, sc[l], off);
    }
    int warp = tid >> 5, lane = tid & 31;
    if (lane == 0) {
#pragma unroll
        for (int l = 0; l < 16; l++) red[l][warp] = sc[l];
    }
    __syncthreads();
    if (tid == 0) {
        float s[16];
        float mx = -1e30f;
#pragma unroll
        for (int l = 0; l < 16; l++) {
            float v = 0.0f;
#pragma unroll
            for (int w = 0; w < 8; w++) v += red[l][w];
            v *= 0.03125f;  // 1/sqrt(1024)
            s[l] = v;
            mx = fmaxf(mx, v);
        }
        float sum = 0.0f;
#pragma unroll
        for (int l = 0; l < 16; l++) { float e = __expf(s[l] - mx); s[l] = e; sum += e; }
        float inv = 1.0f / sum;
#pragma unroll
        for (int l = 0; l < 16; l++) wsm[l] = s[l] * inv;
    }
    __syncthreads();

    float4 w0 = *(float4*)&wsm[0],  w1 = *(float4*)&wsm[4];
    float4 w2 = *(float4*)&wsm[8],  w3 = *(float4*)&wsm[12];
#pragma unroll
    for (int r = 0; r < 4; r++) {
        int hh = tid + r * 256;
        const float4* ar = (const float4*)(An + (size_t)hh * 16);
        float4 a0 = ar[0], a1 = ar[1], a2 = ar[2], a3 = ar[3];
        float v = a0.x * w0.x + a0.y * w0.y + a0.z * w0.z + a0.w * w0.w
                + a1.x * w1.x + a1.y * w1.y + a1.z * w1.z + a1.w * w1.w
                + a2.x * w2.x + a2.y * w2.y + a2.z * w2.z + a2.w * w2.w
                + a3.x * w3.x + a3.y * w3.y + a3.z * w3.z + a3.w * w3.w;
        __nv_bfloat16 hi, lo;
        split_bf16(v, hi, lo);
        ahi_row[1024 + hh] = hi;
        alo_row[1024 + hh] = lo;
    }
}

// =====================================================================
// Init: h0 = mean_l A[n,h,l]; c0 = h0; emit bf16 h0, then attention for step 0.
// =====================================================================
__global__ __launch_bounds__(256) void init_kernel(const float* __restrict__ A)
{
    __shared__ float hs[Hh];
    int n = blockIdx.x;
    int tid = threadIdx.x;
    const float* An = A + (size_t)n * Hh * 16;
    __nv_bfloat16* ahi = g_Ahi + (size_t)n * 2048;
    __nv_bfloat16* alo = g_Alo + (size_t)n * 2048;

#pragma unroll
    for (int r = 0; r < 4; r++) {
        int hh = tid + r * 256;
        const float4* ar = (const float4*)(An + (size_t)hh * 16);
        float4 a0 = ar[0], a1 = ar[1], a2 = ar[2], a3 = ar[3];
        float s = a0.x + a0.y + a0.z + a0.w + a1.x + a1.y + a1.z + a1.w
                + a2.x + a2.y + a2.z + a2.w + a3.x + a3.y + a3.z + a3.w;
        s *= (1.0f / 16.0f);
        g_c[(size_t)n * Hh + hh] = s;
        __nv_bfloat16 hi, lo;
        split_bf16(s, hi, lo);
        ahi[hh] = hi;
        alo[hh] = lo;
        hs[hh] = s;
    }
    __syncthreads();
    attention_block(n, A, hs, ahi, alo, tid);
}

// =====================================================================
// LSTM pointwise (+bias, +4 partials, +xw) + next-step attention.
// =====================================================================
__global__ __launch_bounds__(256) void lstm_attn_kernel(const float* __restrict__ A,
                                                        const float* __restrict__ b,
                                                        float* __restrict__ out, int t)
{
    __shared__ float hs[Hh];
    int n = blockIdx.x;
    int tid = threadIdx.x;
    const float* g0 = g_gp + (size_t)n * G4;
    const float* g1 = g_gp + (size_t)1 * Nn * G4 + (size_t)n * G4;
    const float* g2 = g_gp + (size_t)2 * Nn * G4 + (size_t)n * G4;
    const float* g3 = g_gp + (size_t)3 * Nn * G4 + (size_t)n * G4;
    const float* xw = g_xw + ((size_t)t * Nn + n) * G4;
    __nv_bfloat16* ahi = g_Ahi + (size_t)n * 2048;
    __nv_bfloat16* alo = g_Alo + (size_t)n * 2048;

#pragma unroll
    for (int r = 0; r < 4; r++) {
        int hh = tid + r * 256;
        float gv4[4];
#pragma unroll
        for (int gg = 0; gg < 4; gg++) {
            int o = gg * Hh + hh;
            gv4[gg] = ((g0[o] + g1[o]) + (g2[o] + g3[o])) + (xw[o] + b[o]);
        }
        float c = g_c[(size_t)n * Hh + hh];
        float cn = sigmoidf_(gv4[1]) * c + sigmoidf_(gv4[0]) * tanhf_(gv4[3]);
        float hn = sigmoidf_(gv4[2]) * tanhf_(cn);
        g_c[(size_t)n * Hh + hh] = cn;
        out[(size_t)n * Tt * Hh + (size_t)t * Hh + hh] = hn;
        __nv_bfloat16 hi, lo;
        split_bf16(hn, hi, lo);
        ahi[hh] = hi;
        alo[hh] = lo;
        hs[hh] = hn;
    }
    __syncthreads();
    attention_block(n, A, hs, ahi, alo, tid);
}

// =====================================================================
// launch
// =====================================================================
extern "C" void kernel_launch(void* const* d_in, const int* in_sizes, int n_in,
                              void* d_out, int out_size)
{
    (void)in_sizes; (void)n_in; (void)out_size;
    const float* x     = (const float*)d_in[0];  // (N, T, D)
    const float* A     = (const float*)d_in[1];  // (N, H, 4, 4)
    const float* Wx    = (const float*)d_in[2];  // (D, 4H)
    const float* Wh    = (const float*)d_in[3];  // (H, 4H)
    const float* Wattn = (const float*)d_in[4];  // (H, 4H)
    const float* b     = (const float*)d_in[5];  // (4H,)
    float* out = (float*)d_out;                  // (N, T, H)

    cudaFuncSetAttribute(gemm_step_kernel,
                         cudaFuncAttributeMaxDynamicSharedMemorySize, SMEM_DYN);
    cudaFuncSetAttribute(gemm_xw_kernel,
                         cudaFuncAttributeMaxDynamicSharedMemorySize, SMEM_DYN);

    // one-time prep
    dim3 wgrid(G4 / 32, Ktot / 32);
    wconv_kernel<<<wgrid, 256>>>(Wx, Wh, Wattn);
    xconv_kernel<<<8192, 256>>>(x);
    gemm_xw_kernel<<<dim3(G4 / GBN, (Nn * Tt) / GBM), 256, SMEM_DYN>>>();
    init_kernel<<<Nn, 256>>>(A);

    dim3 gemm_grid(G4 / GBN, Nn / GBM, 4);  // (64, 2, 4) = 512 CTAs
    for (int t = 0; t < Tt; t++) {
        gemm_step_kernel<<<gemm_grid, 256, SMEM_DYN>>>(t);
        lstm_attn_kernel<<<Nn, 256>>>(A, b, out, t);
    }
}

// round 9
// speedup vs baseline: 4.0169x; 1.0126x over previous
#include <cuda_runtime.h>
#include <cuda_bf16.h>
#include <cstdint>
#include <cstddef>

// Problem dims
#define Nn 256
#define Tt 128
#define Dd 512
#define Hh 1024
#define G4 4096            // 4*H
#define Ktot 2560          // W layout rows: Wh (0..1023) | Wattn (1024..2047) | Wx (2048..2559)

// ---------------- scratch (device globals: allocation-free rule) ----------------
__device__ float g_c[Nn * Hh];                          // LSTM cell state (fp32)
__device__ float g_gp[(size_t)2 * Nn * G4];             // per-step GEMM partials (2 K-splits)
__device__ float g_pa[(size_t)Nn * G4];                 // attn contribution to gates (per step)
__device__ float g_xw[(size_t)Tt * Nn * G4];            // precomputed x@Wx, [t][n][4H]
__device__ float g_P[(size_t)Nn * 16 * G4];             // P[(n,l)][col] = A[n,:,l] @ Wattn
__device__ __nv_bfloat16 g_Ahi[(size_t)Nn * Hh];        // h hi
__device__ __nv_bfloat16 g_Alo[(size_t)Nn * Hh];        // h lo
__device__ __nv_bfloat16 g_AThi[(size_t)Nn * 16 * Hh];  // A^T [(n,l)][h] hi
__device__ __nv_bfloat16 g_ATlo[(size_t)Nn * 16 * Hh];  // A^T [(n,l)][h] lo
__device__ __nv_bfloat16 g_xhi[(size_t)Nn * Tt * Dd];   // x hi
__device__ __nv_bfloat16 g_xlo[(size_t)Nn * Tt * Dd];   // x lo
__device__ __nv_bfloat16 g_WThi[(size_t)G4 * Ktot];     // W^T hi: [n][k], K-major
__device__ __nv_bfloat16 g_WTlo[(size_t)G4 * Ktot];     // W^T lo

// ---------------- PTX helpers (sm_80+ baseline features only) ----------------
__device__ __forceinline__ uint32_t smem_to_u32(const void* p) {
    uint32_t a;
    asm("{ .reg .u64 t; cvta.to.shared.u64 t, %1; cvt.u32.u64 %0, t; }" : "=r"(a) : "l"(p));
    return a;
}
#define CP_ASYNC16(dst, src) \
    asm volatile("cp.async.cg.shared.global [%0], [%1], 16;" :: "r"(dst), "l"(src))
#define CP_COMMIT() asm volatile("cp.async.commit_group;" ::: "memory")
#define CP_WAIT0()  asm volatile("cp.async.wait_group 0;" ::: "memory")
#define LDSM_X4(r0, r1, r2, r3, addr)                                             \
    asm volatile("ldmatrix.sync.aligned.m8n8.x4.shared.b16 {%0,%1,%2,%3}, [%4];"  \
        : "=r"(r0), "=r"(r1), "=r"(r2), "=r"(r3) : "r"(addr))

__device__ __forceinline__ void mma16816(float* c, const uint32_t* a,
                                         uint32_t b0, uint32_t b1) {
    asm volatile(
        "mma.sync.aligned.m16n8k16.row.col.f32.bf16.bf16.f32 "
        "{%0,%1,%2,%3}, {%4,%5,%6,%7}, {%8,%9}, {%0,%1,%2,%3};"
        : "+f"(c[0]), "+f"(c[1]), "+f"(c[2]), "+f"(c[3])
        : "r"(a[0]), "r"(a[1]), "r"(a[2]), "r"(a[3]), "r"(b0), "r"(b1));
}

// ---------------- math helpers ----------------
__device__ __forceinline__ float sigmoidf_(float x) { return 1.0f / (1.0f + __expf(-x)); }
__device__ __forceinline__ float tanhf_(float x) {
    float e = __expf(2.0f * x);
    return 1.0f - 2.0f / (e + 1.0f);
}
__device__ __forceinline__ void split_bf16(float v, __nv_bfloat16& hi, __nv_bfloat16& lo) {
    hi = __float2bfloat16(v);
    lo = __float2bfloat16(v - __bfloat162float(hi));
}

// ---------------- shared GEMM tiling ----------------
#define GBM 128
#define GBN 64
#define GBK 32
#define RSTR 80              // smem row stride bytes (32 bf16 + 8 pad)
#define STG 30720            // bytes per pipeline stage
#define AH_OFF(s) ((s) * STG)
#define AL_OFF(s) ((s) * STG + 10240)
#define BH_OFF(s) ((s) * STG + 20480)
#define BL_OFF(s) ((s) * STG + 25600)
#define SMEM_DYN (2 * STG)   // 61440 -> 3 CTAs/SM

// Fragment compute for one chunk stage.
__device__ __forceinline__ void compute_chunk(uint32_t s0, int stage,
                                              uint32_t aOff, uint32_t bOff,
                                              float acc[2][4][4])
{
    const uint32_t ah = s0 + AH_OFF(stage) + aOff;
    const uint32_t al = s0 + AL_OFF(stage) + aOff;
    const uint32_t bh = s0 + BH_OFF(stage) + bOff;
    const uint32_t bl = s0 + BL_OFF(stage) + bOff;
#pragma unroll
    for (int ks = 0; ks < 2; ks++) {
        const uint32_t ko = ks * 32;   // 16 elems * 2B
        uint32_t ahf[2][4], alf[2][4];
        uint32_t bhf[2][4], blf[2][4];
        LDSM_X4(ahf[0][0], ahf[0][1], ahf[0][2], ahf[0][3], ah + ko);
        LDSM_X4(ahf[1][0], ahf[1][1], ahf[1][2], ahf[1][3], ah + 16 * RSTR + ko);
        LDSM_X4(bhf[0][0], bhf[0][1], bhf[0][2], bhf[0][3], bh + ko);
        LDSM_X4(bhf[1][0], bhf[1][1], bhf[1][2], bhf[1][3], bh + 16 * RSTR + ko);
        LDSM_X4(blf[0][0], blf[0][1], blf[0][2], blf[0][3], bl + ko);
        LDSM_X4(blf[1][0], blf[1][1], blf[1][2], blf[1][3], bl + 16 * RSTR + ko);
        LDSM_X4(alf[0][0], alf[0][1], alf[0][2], alf[0][3], al + ko);
        LDSM_X4(alf[1][0], alf[1][1], alf[1][2], alf[1][3], al + 16 * RSTR + ko);
#pragma unroll
        for (int mf = 0; mf < 2; mf++) {
#pragma unroll
            for (int nf = 0; nf < 4; nf++) {
                const uint32_t b0 = bhf[nf >> 1][(nf & 1) * 2];
                const uint32_t b1 = bhf[nf >> 1][(nf & 1) * 2 + 1];
                mma16816(acc[mf][nf], ahf[mf], b0, b1);           // hi*hi
                mma16816(acc[mf][nf], alf[mf], b0, b1);           // lo*hi
                mma16816(acc[mf][nf], ahf[mf],                    // hi*lo
                         blf[nf >> 1][(nf & 1) * 2], blf[nf >> 1][(nf & 1) * 2 + 1]);
            }
        }
    }
}

// =====================================================================
// One-time: W^T hi/lo. WT[n][k] = bf16split(W[k][n]); K rows: Wh|Wattn|Wx
// =====================================================================
__global__ __launch_bounds__(256) void wconv_kernel(const float* __restrict__ Wx,
                                                    const float* __restrict__ Wh,
                                                    const float* __restrict__ Wattn)
{
    __shared__ float tile[32][33];
    const int nt = blockIdx.x * 32;
    const int kt = blockIdx.y * 32;
    const int tx = threadIdx.x & 31, ty = threadIdx.x >> 5;
#pragma unroll
    for (int r = 0; r < 4; r++) {
        int k = kt + ty + r * 8;
        int n = nt + tx;
        const float* src;
        if (k < 1024)       src = Wh    + (size_t)k * G4;
        else if (k < 2048)  src = Wattn + (size_t)(k - 1024) * G4;
        else                src = Wx    + (size_t)(k - 2048) * G4;
        tile[ty + r * 8][tx] = src[n];
    }
    __syncthreads();
#pragma unroll
    for (int r = 0; r < 4; r++) {
        int n = nt + ty + r * 8;
        int k = kt + tx;
        float v = tile[tx][ty + r * 8];
        __nv_bfloat16 hi, lo;
        split_bf16(v, hi, lo);
        g_WThi[(size_t)n * Ktot + k] = hi;
        g_WTlo[(size_t)n * Ktot + k] = lo;
    }
}

// One-time: x -> bf16 hi/lo
__global__ __launch_bounds__(256) void xconv_kernel(const float* __restrict__ x)
{
    const size_t total = (size_t)Nn * Tt * Dd;
    for (size_t i = (size_t)blockIdx.x * blockDim.x + threadIdx.x; i < total;
         i += (size_t)gridDim.x * blockDim.x) {
        __nv_bfloat16 hi, lo;
        split_bf16(x[i], hi, lo);
        g_xhi[i] = hi;
        g_xlo[i] = lo;
    }
}

// One-time: A[n][h][l] -> A^T [(n*16+l)][h] bf16 hi/lo
__global__ __launch_bounds__(256) void aconv_kernel(const float* __restrict__ A)
{
    const int n = blockIdx.x;
    const float* An = A + (size_t)n * Hh * 16;
    for (int idx = threadIdx.x; idx < Hh * 16; idx += 256) {
        const int h = idx >> 4, l = idx & 15;
        __nv_bfloat16 hi, lo;
        split_bf16(An[idx], hi, lo);
        const size_t o = ((size_t)(n * 16 + l)) * Hh + h;
        g_AThi[o] = hi;
        g_ATlo[o] = lo;
    }
}

// =====================================================================
// One-time GEMM: P[(n,l)][:] = A^T[(n,l)][:] @ Wattn  (bf16 hi/lo x3)
// M = 4096, K = 1024, N = 4096. Grid (64, 32) = 2048 CTAs.
// =====================================================================
__global__ __launch_bounds__(256, 3) void gemm_P_kernel()
{
    extern __shared__ __align__(128) __nv_bfloat16 dsm[];
    const uint32_t s0 = smem_to_u32(dsm);
    const int tid = threadIdx.x;
    const int lane = tid & 31;
    const int w = tid >> 5;
    const int wm = w & 3, wn = w >> 2;
    const int bn = blockIdx.x * GBN;
    const int bm = blockIdx.y * GBM;

    const int a_row = tid >> 2, a_seg = tid & 3;
    const int b_row = tid >> 2, b_seg = tid & 3;
    const uint32_t aOff = (uint32_t)((wm * 32 + (lane & 15)) * RSTR + (lane >> 4) * 16);
    const int brow = (lane & 7) + ((lane >> 4) << 3);
    const uint32_t bOff = (uint32_t)((wn * 32 + brow) * RSTR + ((lane >> 3) & 1) * 16);

    auto issue = [&](int c, int s) {
        const int kc = c * GBK;
        {
            const size_t o = (size_t)(bn + b_row) * Ktot + 1024 + kc + b_seg * 8;
            CP_ASYNC16(s0 + BH_OFF(s) + b_row * RSTR + b_seg * 16, g_WThi + o);
            CP_ASYNC16(s0 + BL_OFF(s) + b_row * RSTR + b_seg * 16, g_WTlo + o);
        }
#pragma unroll
        for (int r = 0; r < 2; r++) {
            const int m = a_row + r * 64;
            const size_t o = (size_t)(bm + m) * Hh + kc + a_seg * 8;
            const uint32_t d = m * RSTR + a_seg * 16;
            CP_ASYNC16(s0 + AH_OFF(s) + d, g_AThi + o);
            CP_ASYNC16(s0 + AL_OFF(s) + d, g_ATlo + o);
        }
    };

    float acc[2][4][4];
#pragma unroll
    for (int mf = 0; mf < 2; mf++)
#pragma unroll
        for (int nf = 0; nf < 4; nf++)
#pragma unroll
            for (int i = 0; i < 4; i++) acc[mf][nf][i] = 0.0f;

    const int NCH = Hh / GBK;  // 32
    issue(0, 0); CP_COMMIT();
    for (int it = 0; it < NCH; it++) {
        CP_WAIT0();
        __syncthreads();
        if (it + 1 < NCH) { issue(it + 1, (it + 1) & 1); CP_COMMIT(); }
        compute_chunk(s0, it & 1, aOff, bOff, acc);
    }

#pragma unroll
    for (int mf = 0; mf < 2; mf++) {
        const int row0 = bm + wm * 32 + mf * 16 + (lane >> 2);
#pragma unroll
        for (int nf = 0; nf < 4; nf++) {
            const int col = bn + wn * 32 + nf * 8 + (lane & 3) * 2;
            *(float2*)&g_P[(size_t)row0 * G4 + col] =
                make_float2(acc[mf][nf][0], acc[mf][nf][1]);
            *(float2*)&g_P[(size_t)(row0 + 8) * G4 + col] =
                make_float2(acc[mf][nf][2], acc[mf][nf][3]);
        }
    }
}

// =====================================================================
// One-time big GEMM: xw[t][n][:] = x[n][t][:] @ Wx   (bf16 hi/lo x3)
// M = N*T = 32768 (row m = n*128 + t), K = 512, N = 4096. Grid (64, 256).
// =====================================================================
__global__ __launch_bounds__(256, 3) void gemm_xw_kernel()
{
    extern __shared__ __align__(128) __nv_bfloat16 dsm[];
    const uint32_t s0 = smem_to_u32(dsm);
    const int tid = threadIdx.x;
    const int lane = tid & 31;
    const int w = tid >> 5;
    const int wm = w & 3, wn = w >> 2;
    const int bn = blockIdx.x * GBN;
    const int bm = blockIdx.y * GBM;

    const int a_row = tid >> 2, a_seg = tid & 3;
    const int b_row = tid >> 2, b_seg = tid & 3;
    const uint32_t aOff = (uint32_t)((wm * 32 + (lane & 15)) * RSTR + (lane >> 4) * 16);
    const int brow = (lane & 7) + ((lane >> 4) << 3);
    const uint32_t bOff = (uint32_t)((wn * 32 + brow) * RSTR + ((lane >> 3) & 1) * 16);

    auto issue = [&](int c, int s) {
        const int kc = c * GBK;
        {
            const size_t o = (size_t)(bn + b_row) * Ktot + 2048 + kc + b_seg * 8;
            CP_ASYNC16(s0 + BH_OFF(s) + b_row * RSTR + b_seg * 16, g_WThi + o);
            CP_ASYNC16(s0 + BL_OFF(s) + b_row * RSTR + b_seg * 16, g_WTlo + o);
        }
#pragma unroll
        for (int r = 0; r < 2; r++) {
            const int m = a_row + r * 64;
            const size_t o = (size_t)(bm + m) * Dd + kc + a_seg * 8;
            const uint32_t d = m * RSTR + a_seg * 16;
            CP_ASYNC16(s0 + AH_OFF(s) + d, g_xhi + o);
            CP_ASYNC16(s0 + AL_OFF(s) + d, g_xlo + o);
        }
    };

    float acc[2][4][4];
#pragma unroll
    for (int mf = 0; mf < 2; mf++)
#pragma unroll
        for (int nf = 0; nf < 4; nf++)
#pragma unroll
            for (int i = 0; i < 4; i++) acc[mf][nf][i] = 0.0f;

    const int NCH = Dd / GBK;  // 16
    issue(0, 0); CP_COMMIT();
    for (int it = 0; it < NCH; it++) {
        CP_WAIT0();
        __syncthreads();
        if (it + 1 < NCH) { issue(it + 1, (it + 1) & 1); CP_COMMIT(); }
        compute_chunk(s0, it & 1, aOff, bOff, acc);
    }

#pragma unroll
    for (int mf = 0; mf < 2; mf++) {
        const int m0 = bm + wm * 32 + mf * 16 + (lane >> 2);
#pragma unroll
        for (int pr = 0; pr < 2; pr++) {
            const int m = m0 + pr * 8;
            float* xrow = g_xw + ((size_t)(m & 127) * Nn + (m >> 7)) * G4;
#pragma unroll
            for (int nf = 0; nf < 4; nf++) {
                const int col = bn + wn * 32 + nf * 8 + (lane & 3) * 2;
                *(float2*)&xrow[col] =
                    make_float2(acc[mf][nf][pr * 2], acc[mf][nf][pr * 2 + 1]);
            }
        }
    }
}

// =====================================================================
// Per-step GEMM: gp[kz] = h(:, Kz) @ Wh(Kz, :). K = 1024, split x2.
// Grid (64, 2, 2) = 256 CTAs, 16 chunks each.
// =====================================================================
__global__ __launch_bounds__(256, 3) void gemm_step_kernel()
{
    extern __shared__ __align__(128) __nv_bfloat16 dsm[];
    const uint32_t s0 = smem_to_u32(dsm);
    const int tid = threadIdx.x;
    const int lane = tid & 31;
    const int w = tid >> 5;
    const int wm = w & 3, wn = w >> 2;
    const int bn = blockIdx.x * GBN;
    const int bm = blockIdx.y * GBM;
    const int kz = blockIdx.z;
    const int kbase = kz * 512;

    const int a_row = tid >> 2, a_seg = tid & 3;
    const int b_row = tid >> 2, b_seg = tid & 3;
    const uint32_t aOff = (uint32_t)((wm * 32 + (lane & 15)) * RSTR + (lane >> 4) * 16);
    const int brow = (lane & 7) + ((lane >> 4) << 3);
    const uint32_t bOff = (uint32_t)((wn * 32 + brow) * RSTR + ((lane >> 3) & 1) * 16);

    auto issue = [&](int c, int s) {
        const int kc = kbase + c * GBK;
        {
            const size_t o = (size_t)(bn + b_row) * Ktot + kc + b_seg * 8;
            CP_ASYNC16(s0 + BH_OFF(s) + b_row * RSTR + b_seg * 16, g_WThi + o);
            CP_ASYNC16(s0 + BL_OFF(s) + b_row * RSTR + b_seg * 16, g_WTlo + o);
        }
#pragma unroll
        for (int r = 0; r < 2; r++) {
            const int m = a_row + r * 64;
            const size_t o = (size_t)(bm + m) * Hh + kc + a_seg * 8;
            const uint32_t d = m * RSTR + a_seg * 16;
            CP_ASYNC16(s0 + AH_OFF(s) + d, g_Ahi + o);
            CP_ASYNC16(s0 + AL_OFF(s) + d, g_Alo + o);
        }
    };

    float acc[2][4][4];
#pragma unroll
    for (int mf = 0; mf < 2; mf++)
#pragma unroll
        for (int nf = 0; nf < 4; nf++)
#pragma unroll
            for (int i = 0; i < 4; i++) acc[mf][nf][i] = 0.0f;

    const int NCH = 512 / GBK;  // 16
    issue(0, 0); CP_COMMIT();
    for (int it = 0; it < NCH; it++) {
        CP_WAIT0();
        __syncthreads();
        if (it + 1 < NCH) { issue(it + 1, (it + 1) & 1); CP_COMMIT(); }
        compute_chunk(s0, it & 1, aOff, bOff, acc);
    }

    float* gpart = g_gp + (size_t)kz * Nn * G4;
#pragma unroll
    for (int mf = 0; mf < 2; mf++) {
        const int row0 = bm + wm * 32 + mf * 16 + (lane >> 2);
#pragma unroll
        for (int nf = 0; nf < 4; nf++) {
            const int col = bn + wn * 32 + nf * 8 + (lane & 3) * 2;
            *(float2*)&gpart[(size_t)row0 * G4 + col] =
                make_float2(acc[mf][nf][0], acc[mf][nf][1]);
            *(float2*)&gpart[(size_t)(row0 + 8) * G4 + col] =
                make_float2(acc[mf][nf][2], acc[mf][nf][3]);
        }
    }
}

// =====================================================================
// Attention weights (softmax over 16 locations) + P-weighted sum -> g_pa.
// hs = current h (fp32, smem). Runs inside init and lstm kernels.
// =====================================================================
__device__ __forceinline__ void attn_psum(int n, const float* __restrict__ A,
                                          const float* hs, int tid)
{
    __shared__ float red[16][8];
    __shared__ float wsm[16];

    const float* An = A + (size_t)n * Hh * 16;

    float sc[16];
#pragma unroll
    for (int l = 0; l < 16; l++) sc[l] = 0.0f;

#pragma unroll
    for (int r = 0; r < 4; r++) {
        int hh = tid + r * 256;
        float hv = hs[hh];
        const float4* ar = (const float4*)(An + (size_t)hh * 16);
        float4 a0 = ar[0], a1 = ar[1], a2 = ar[2], a3 = ar[3];
        sc[0]  += a0.x * hv; sc[1]  += a0.y * hv; sc[2]  += a0.z * hv; sc[3]  += a0.w * hv;
        sc[4]  += a1.x * hv; sc[5]  += a1.y * hv; sc[6]  += a1.z * hv; sc[7]  += a1.w * hv;
        sc[8]  += a2.x * hv; sc[9]  += a2.y * hv; sc[10] += a2.z * hv; sc[11] += a2.w * hv;
        sc[12] += a3.x * hv; sc[13] += a3.y * hv; sc[14] += a3.z * hv; sc[15] += a3.w * hv;
    }
#pragma unroll
    for (int l = 0; l < 16; l++) {
#pragma unroll
        for (int off = 16; off > 0; off >>= 1)
            sc[l] += __shfl_xor_sync(0xffffffffu, sc[l], off);
    }
    int warp = tid >> 5, lane = tid & 31;
    if (lane == 0) {
#pragma unroll
        for (int l = 0; l < 16; l++) red[l][warp] = sc[l];
    }
    __syncthreads();
    if (tid == 0) {
        float s[16];
        float mx = -1e30f;
#pragma unroll
        for (int l = 0; l < 16; l++) {
            float v = 0.0f;
#pragma unroll
            for (int w = 0; w < 8; w++) v += red[l][w];
            v *= 0.03125f;  // 1/sqrt(1024)
            s[l] = v;
            mx = fmaxf(mx, v);
        }
        float sum = 0.0f;
#pragma unroll
        for (int l = 0; l < 16; l++) { float e = __expf(s[l] - mx); s[l] = e; sum += e; }
        float inv = 1.0f / sum;
#pragma unroll
        for (int l = 0; l < 16; l++) wsm[l] = s[l] * inv;
    }
    __syncthreads();

    // attn-gates contribution: g_pa[n][c] = sum_l wsm[l] * P[(n,l)][c]
    float s[16];
#pragma unroll
    for (int i = 0; i < 16; i++) s[i] = 0.0f;
#pragma unroll
    for (int l = 0; l < 16; l++) {
        const float wl = wsm[l];
        const float* Pr = g_P + ((size_t)(n * 16 + l)) * G4;
#pragma unroll
        for (int i = 0; i < 16; i++) s[i] += wl * Pr[tid + i * 256];
    }
    float* pa = g_pa + (size_t)n * G4;
#pragma unroll
    for (int i = 0; i < 16; i++) pa[tid + i * 256] = s[i];
}

// =====================================================================
// Init: h0 = mean_l A[n,h,l]; c0 = h0; emit bf16 h0; wsm + P-sum for step 0.
// =====================================================================
__global__ __launch_bounds__(256) void init_kernel(const float* __restrict__ A)
{
    __shared__ float hs[Hh];
    int n = blockIdx.x;
    int tid = threadIdx.x;
    const float* An = A + (size_t)n * Hh * 16;

#pragma unroll
    for (int r = 0; r < 4; r++) {
        int hh = tid + r * 256;
        const float4* ar = (const float4*)(An + (size_t)hh * 16);
        float4 a0 = ar[0], a1 = ar[1], a2 = ar[2], a3 = ar[3];
        float s = a0.x + a0.y + a0.z + a0.w + a1.x + a1.y + a1.z + a1.w
                + a2.x + a2.y + a2.z + a2.w + a3.x + a3.y + a3.z + a3.w;
        s *= (1.0f / 16.0f);
        g_c[(size_t)n * Hh + hh] = s;
        __nv_bfloat16 hi, lo;
        split_bf16(s, hi, lo);
        g_Ahi[(size_t)n * Hh + hh] = hi;
        g_Alo[(size_t)n * Hh + hh] = lo;
        hs[hh] = s;
    }
    __syncthreads();
    attn_psum(n, A, hs, tid);
}

// =====================================================================
// LSTM pointwise (gates = gp0+gp1+xw+pa+b) + next-step wsm/P-sum.
// =====================================================================
__global__ __launch_bounds__(256) void lstm_attn_kernel(const float* __restrict__ A,
                                                        const float* __restrict__ b,
                                                        float* __restrict__ out, int t)
{
    __shared__ float hs[Hh];
    int n = blockIdx.x;
    int tid = threadIdx.x;
    const float* g0 = g_gp + (size_t)n * G4;
    const float* g1 = g_gp + (size_t)Nn * G4 + (size_t)n * G4;
    const float* xw = g_xw + ((size_t)t * Nn + n) * G4;
    const float* pa = g_pa + (size_t)n * G4;

#pragma unroll
    for (int r = 0; r < 4; r++) {
        int hh = tid + r * 256;
        float gv4[4];
#pragma unroll
        for (int gg = 0; gg < 4; gg++) {
            int o = gg * Hh + hh;
            gv4[gg] = ((g0[o] + g1[o]) + (xw[o] + pa[o])) + b[o];
        }
        float c = g_c[(size_t)n * Hh + hh];
        float cn = sigmoidf_(gv4[1]) * c + sigmoidf_(gv4[0]) * tanhf_(gv4[3]);
        float hn = sigmoidf_(gv4[2]) * tanhf_(cn);
        g_c[(size_t)n * Hh + hh] = cn;
        out[(size_t)n * Tt * Hh + (size_t)t * Hh + hh] = hn;
        __nv_bfloat16 hi, lo;
        split_bf16(hn, hi, lo);
        g_Ahi[(size_t)n * Hh + hh] = hi;
        g_Alo[(size_t)n * Hh + hh] = lo;
        hs[hh] = hn;
    }
    __syncthreads();
    attn_psum(n, A, hs, tid);
}

// =====================================================================
// launch
// =====================================================================
extern "C" void kernel_launch(void* const* d_in, const int* in_sizes, int n_in,
                              void* d_out, int out_size)
{
    (void)in_sizes; (void)n_in; (void)out_size;
    const float* x     = (const float*)d_in[0];  // (N, T, D)
    const float* A     = (const float*)d_in[1];  // (N, H, 4, 4)
    const float* Wx    = (const float*)d_in[2];  // (D, 4H)
    const float* Wh    = (const float*)d_in[3];  // (H, 4H)
    const float* Wattn = (const float*)d_in[4];  // (H, 4H)
    const float* b     = (const float*)d_in[5];  // (4H,)
    float* out = (float*)d_out;                  // (N, T, H)

    cudaFuncSetAttribute(gemm_step_kernel,
                         cudaFuncAttributeMaxDynamicSharedMemorySize, SMEM_DYN);
    cudaFuncSetAttribute(gemm_xw_kernel,
                         cudaFuncAttributeMaxDynamicSharedMemorySize, SMEM_DYN);
    cudaFuncSetAttribute(gemm_P_kernel,
                         cudaFuncAttributeMaxDynamicSharedMemorySize, SMEM_DYN);

    // one-time prep
    dim3 wgrid(G4 / 32, Ktot / 32);
    wconv_kernel<<<wgrid, 256>>>(Wx, Wh, Wattn);
    xconv_kernel<<<8192, 256>>>(x);
    aconv_kernel<<<Nn, 256>>>(A);
    gemm_P_kernel<<<dim3(G4 / GBN, (Nn * 16) / GBM), 256, SMEM_DYN>>>();
    gemm_xw_kernel<<<dim3(G4 / GBN, (Nn * Tt) / GBM), 256, SMEM_DYN>>>();
    init_kernel<<<Nn, 256>>>(A);

    dim3 gemm_grid(G4 / GBN, Nn / GBM, 2);  // (64, 2, 2) = 256 CTAs
    for (int t = 0; t < Tt; t++) {
        gemm_step_kernel<<<gemm_grid, 256, SMEM_DYN>>>();
        lstm_attn_kernel<<<Nn, 256>>>(A, b, out, t);
    }
}

// round 10
// speedup vs baseline: 5.2133x; 1.2978x over previous
#include <cuda_runtime.h>
#include <cuda_bf16.h>
#include <cstdint>
#include <cstddef>

// Problem dims
#define Nn 256
#define Tt 128
#define Dd 512
#define Hh 1024
#define G4 4096            // 4*H
#define Ktot 2560          // W layout rows: Wh (0..1023) | Wattn (1024..2047) | Wx (2048..2559)

// ---------------- scratch (device globals: allocation-free rule) ----------------
__device__ float g_c[Nn * Hh];                          // LSTM cell state (fp32)
__device__ float g_h[Nn * Hh];                          // current h (fp32)
__device__ float g_gp[(size_t)2 * Nn * G4];             // per-step GEMM partials (2 K-splits)
__device__ float g_pa[(size_t)Nn * G4];                 // attn contribution to gates (per step)
__device__ float g_xw[(size_t)Tt * Nn * G4];            // precomputed x@Wx, [t][n][4H]
__device__ float g_P[(size_t)Nn * 16 * G4];             // P[(n,l)][col] = A[n,:,l] @ Wattn
__device__ __nv_bfloat16 g_Ahi[(size_t)Nn * Hh];        // h hi
__device__ __nv_bfloat16 g_Alo[(size_t)Nn * Hh];        // h lo
__device__ __nv_bfloat16 g_AThi[(size_t)Nn * 16 * Hh];  // A^T [(n,l)][h] hi
__device__ __nv_bfloat16 g_ATlo[(size_t)Nn * 16 * Hh];  // A^T [(n,l)][h] lo
__device__ __nv_bfloat16 g_xhi[(size_t)Nn * Tt * Dd];   // x hi
__device__ __nv_bfloat16 g_xlo[(size_t)Nn * Tt * Dd];   // x lo
__device__ __nv_bfloat16 g_WThi[(size_t)G4 * Ktot];     // W^T hi: [n][k], K-major
__device__ __nv_bfloat16 g_WTlo[(size_t)G4 * Ktot];     // W^T lo

// ---------------- PTX helpers (sm_80+ baseline features only) ----------------
__device__ __forceinline__ uint32_t smem_to_u32(const void* p) {
    uint32_t a;
    asm("{ .reg .u64 t; cvta.to.shared.u64 t, %1; cvt.u32.u64 %0, t; }" : "=r"(a) : "l"(p));
    return a;
}
#define CP_ASYNC16(dst, src) \
    asm volatile("cp.async.cg.shared.global [%0], [%1], 16;" :: "r"(dst), "l"(src))
#define CP_COMMIT() asm volatile("cp.async.commit_group;" ::: "memory")
#define CP_WAIT0()  asm volatile("cp.async.wait_group 0;" ::: "memory")
#define LDSM_X4(r0, r1, r2, r3, addr)                                             \
    asm volatile("ldmatrix.sync.aligned.m8n8.x4.shared.b16 {%0,%1,%2,%3}, [%4];"  \
        : "=r"(r0), "=r"(r1), "=r"(r2), "=r"(r3) : "r"(addr))

__device__ __forceinline__ void mma16816(float* c, const uint32_t* a,
                                         uint32_t b0, uint32_t b1) {
    asm volatile(
        "mma.sync.aligned.m16n8k16.row.col.f32.bf16.bf16.f32 "
        "{%0,%1,%2,%3}, {%4,%5,%6,%7}, {%8,%9}, {%0,%1,%2,%3};"
        : "+f"(c[0]), "+f"(c[1]), "+f"(c[2]), "+f"(c[3])
        : "r"(a[0]), "r"(a[1]), "r"(a[2]), "r"(a[3]), "r"(b0), "r"(b1));
}

// ---------------- math helpers ----------------
__device__ __forceinline__ float sigmoidf_(float x) { return 1.0f / (1.0f + __expf(-x)); }
__device__ __forceinline__ float tanhf_(float x) {
    float e = __expf(2.0f * x);
    return 1.0f - 2.0f / (e + 1.0f);
}
__device__ __forceinline__ void split_bf16(float v, __nv_bfloat16& hi, __nv_bfloat16& lo) {
    hi = __float2bfloat16(v);
    lo = __float2bfloat16(v - __bfloat162float(hi));
}

// ---------------- shared GEMM tiling ----------------
#define GBM 128
#define GBN 64
#define GBK 32
#define RSTR 80              // smem row stride bytes (32 bf16 + 8 pad)
#define STG 30720            // bytes per pipeline stage
#define AH_OFF(s) ((s) * STG)
#define AL_OFF(s) ((s) * STG + 10240)
#define BH_OFF(s) ((s) * STG + 20480)
#define BL_OFF(s) ((s) * STG + 25600)
#define SMEM_DYN (2 * STG)   // 61440 -> 3 CTAs/SM

// Fragment compute for one chunk stage.
__device__ __forceinline__ void compute_chunk(uint32_t s0, int stage,
                                              uint32_t aOff, uint32_t bOff,
                                              float acc[2][4][4])
{
    const uint32_t ah = s0 + AH_OFF(stage) + aOff;
    const uint32_t al = s0 + AL_OFF(stage) + aOff;
    const uint32_t bh = s0 + BH_OFF(stage) + bOff;
    const uint32_t bl = s0 + BL_OFF(stage) + bOff;
#pragma unroll
    for (int ks = 0; ks < 2; ks++) {
        const uint32_t ko = ks * 32;   // 16 elems * 2B
        uint32_t ahf[2][4], alf[2][4];
        uint32_t bhf[2][4], blf[2][4];
        LDSM_X4(ahf[0][0], ahf[0][1], ahf[0][2], ahf[0][3], ah + ko);
        LDSM_X4(ahf[1][0], ahf[1][1], ahf[1][2], ahf[1][3], ah + 16 * RSTR + ko);
        LDSM_X4(bhf[0][0], bhf[0][1], bhf[0][2], bhf[0][3], bh + ko);
        LDSM_X4(bhf[1][0], bhf[1][1], bhf[1][2], bhf[1][3], bh + 16 * RSTR + ko);
        LDSM_X4(blf[0][0], blf[0][1], blf[0][2], blf[0][3], bl + ko);
        LDSM_X4(blf[1][0], blf[1][1], blf[1][2], blf[1][3], bl + 16 * RSTR + ko);
        LDSM_X4(alf[0][0], alf[0][1], alf[0][2], alf[0][3], al + ko);
        LDSM_X4(alf[1][0], alf[1][1], alf[1][2], alf[1][3], al + 16 * RSTR + ko);
#pragma unroll
        for (int mf = 0; mf < 2; mf++) {
#pragma unroll
            for (int nf = 0; nf < 4; nf++) {
                const uint32_t b0 = bhf[nf >> 1][(nf & 1) * 2];
                const uint32_t b1 = bhf[nf >> 1][(nf & 1) * 2 + 1];
                mma16816(acc[mf][nf], ahf[mf], b0, b1);           // hi*hi
                mma16816(acc[mf][nf], alf[mf], b0, b1);           // lo*hi
                mma16816(acc[mf][nf], ahf[mf],                    // hi*lo
                         blf[nf >> 1][(nf & 1) * 2], blf[nf >> 1][(nf & 1) * 2 + 1]);
            }
        }
    }
}

// =====================================================================
// One-time: W^T hi/lo. WT[n][k] = bf16split(W[k][n]); K rows: Wh|Wattn|Wx
// =====================================================================
__global__ __launch_bounds__(256) void wconv_kernel(const float* __restrict__ Wx,
                                                    const float* __restrict__ Wh,
                                                    const float* __restrict__ Wattn)
{
    __shared__ float tile[32][33];
    const int nt = blockIdx.x * 32;
    const int kt = blockIdx.y * 32;
    const int tx = threadIdx.x & 31, ty = threadIdx.x >> 5;
#pragma unroll
    for (int r = 0; r < 4; r++) {
        int k = kt + ty + r * 8;
        int n = nt + tx;
        const float* src;
        if (k < 1024)       src = Wh    + (size_t)k * G4;
        else if (k < 2048)  src = Wattn + (size_t)(k - 1024) * G4;
        else                src = Wx    + (size_t)(k - 2048) * G4;
        tile[ty + r * 8][tx] = src[n];
    }
    __syncthreads();
#pragma unroll
    for (int r = 0; r < 4; r++) {
        int n = nt + ty + r * 8;
        int k = kt + tx;
        float v = tile[tx][ty + r * 8];
        __nv_bfloat16 hi, lo;
        split_bf16(v, hi, lo);
        g_WThi[(size_t)n * Ktot + k] = hi;
        g_WTlo[(size_t)n * Ktot + k] = lo;
    }
}

// One-time: x -> bf16 hi/lo
__global__ __launch_bounds__(256) void xconv_kernel(const float* __restrict__ x)
{
    const size_t total = (size_t)Nn * Tt * Dd;
    for (size_t i = (size_t)blockIdx.x * blockDim.x + threadIdx.x; i < total;
         i += (size_t)gridDim.x * blockDim.x) {
        __nv_bfloat16 hi, lo;
        split_bf16(x[i], hi, lo);
        g_xhi[i] = hi;
        g_xlo[i] = lo;
    }
}

// One-time: A[n][h][l] -> A^T [(n*16+l)][h] bf16 hi/lo
__global__ __launch_bounds__(256) void aconv_kernel(const float* __restrict__ A)
{
    const int n = blockIdx.x;
    const float* An = A + (size_t)n * Hh * 16;
    for (int idx = threadIdx.x; idx < Hh * 16; idx += 256) {
        const int h = idx >> 4, l = idx & 15;
        __nv_bfloat16 hi, lo;
        split_bf16(An[idx], hi, lo);
        const size_t o = ((size_t)(n * 16 + l)) * Hh + h;
        g_AThi[o] = hi;
        g_ATlo[o] = lo;
    }
}

// =====================================================================
// One-time GEMM: P[(n,l)][:] = A^T[(n,l)][:] @ Wattn  (bf16 hi/lo x3)
// =====================================================================
__global__ __launch_bounds__(256, 3) void gemm_P_kernel()
{
    extern __shared__ __align__(128) __nv_bfloat16 dsm[];
    const uint32_t s0 = smem_to_u32(dsm);
    const int tid = threadIdx.x;
    const int lane = tid & 31;
    const int w = tid >> 5;
    const int wm = w & 3, wn = w >> 2;
    const int bn = blockIdx.x * GBN;
    const int bm = blockIdx.y * GBM;

    const int a_row = tid >> 2, a_seg = tid & 3;
    const int b_row = tid >> 2, b_seg = tid & 3;
    const uint32_t aOff = (uint32_t)((wm * 32 + (lane & 15)) * RSTR + (lane >> 4) * 16);
    const int brow = (lane & 7) + ((lane >> 4) << 3);
    const uint32_t bOff = (uint32_t)((wn * 32 + brow) * RSTR + ((lane >> 3) & 1) * 16);

    auto issue = [&](int c, int s) {
        const int kc = c * GBK;
        {
            const size_t o = (size_t)(bn + b_row) * Ktot + 1024 + kc + b_seg * 8;
            CP_ASYNC16(s0 + BH_OFF(s) + b_row * RSTR + b_seg * 16, g_WThi + o);
            CP_ASYNC16(s0 + BL_OFF(s) + b_row * RSTR + b_seg * 16, g_WTlo + o);
        }
#pragma unroll
        for (int r = 0; r < 2; r++) {
            const int m = a_row + r * 64;
            const size_t o = (size_t)(bm + m) * Hh + kc + a_seg * 8;
            const uint32_t d = m * RSTR + a_seg * 16;
            CP_ASYNC16(s0 + AH_OFF(s) + d, g_AThi + o);
            CP_ASYNC16(s0 + AL_OFF(s) + d, g_ATlo + o);
        }
    };

    float acc[2][4][4];
#pragma unroll
    for (int mf = 0; mf < 2; mf++)
#pragma unroll
        for (int nf = 0; nf < 4; nf++)
#pragma unroll
            for (int i = 0; i < 4; i++) acc[mf][nf][i] = 0.0f;

    const int NCH = Hh / GBK;  // 32
    issue(0, 0); CP_COMMIT();
    for (int it = 0; it < NCH; it++) {
        CP_WAIT0();
        __syncthreads();
        if (it + 1 < NCH) { issue(it + 1, (it + 1) & 1); CP_COMMIT(); }
        compute_chunk(s0, it & 1, aOff, bOff, acc);
    }

#pragma unroll
    for (int mf = 0; mf < 2; mf++) {
        const int row0 = bm + wm * 32 + mf * 16 + (lane >> 2);
#pragma unroll
        for (int nf = 0; nf < 4; nf++) {
            const int col = bn + wn * 32 + nf * 8 + (lane & 3) * 2;
            *(float2*)&g_P[(size_t)row0 * G4 + col] =
                make_float2(acc[mf][nf][0], acc[mf][nf][1]);
            *(float2*)&g_P[(size_t)(row0 + 8) * G4 + col] =
                make_float2(acc[mf][nf][2], acc[mf][nf][3]);
        }
    }
}

// =====================================================================
// One-time big GEMM: xw[t][n][:] = x[n][t][:] @ Wx   (bf16 hi/lo x3)
// =====================================================================
__global__ __launch_bounds__(256, 3) void gemm_xw_kernel()
{
    extern __shared__ __align__(128) __nv_bfloat16 dsm[];
    const uint32_t s0 = smem_to_u32(dsm);
    const int tid = threadIdx.x;
    const int lane = tid & 31;
    const int w = tid >> 5;
    const int wm = w & 3, wn = w >> 2;
    const int bn = blockIdx.x * GBN;
    const int bm = blockIdx.y * GBM;

    const int a_row = tid >> 2, a_seg = tid & 3;
    const int b_row = tid >> 2, b_seg = tid & 3;
    const uint32_t aOff = (uint32_t)((wm * 32 + (lane & 15)) * RSTR + (lane >> 4) * 16);
    const int brow = (lane & 7) + ((lane >> 4) << 3);
    const uint32_t bOff = (uint32_t)((wn * 32 + brow) * RSTR + ((lane >> 3) & 1) * 16);

    auto issue = [&](int c, int s) {
        const int kc = c * GBK;
        {
            const size_t o = (size_t)(bn + b_row) * Ktot + 2048 + kc + b_seg * 8;
            CP_ASYNC16(s0 + BH_OFF(s) + b_row * RSTR + b_seg * 16, g_WThi + o);
            CP_ASYNC16(s0 + BL_OFF(s) + b_row * RSTR + b_seg * 16, g_WTlo + o);
        }
#pragma unroll
        for (int r = 0; r < 2; r++) {
            const int m = a_row + r * 64;
            const size_t o = (size_t)(bm + m) * Dd + kc + a_seg * 8;
            const uint32_t d = m * RSTR + a_seg * 16;
            CP_ASYNC16(s0 + AH_OFF(s) + d, g_xhi + o);
            CP_ASYNC16(s0 + AL_OFF(s) + d, g_xlo + o);
        }
    };

    float acc[2][4][4];
#pragma unroll
    for (int mf = 0; mf < 2; mf++)
#pragma unroll
        for (int nf = 0; nf < 4; nf++)
#pragma unroll
            for (int i = 0; i < 4; i++) acc[mf][nf][i] = 0.0f;

    const int NCH = Dd / GBK;  // 16
    issue(0, 0); CP_COMMIT();
    for (int it = 0; it < NCH; it++) {
        CP_WAIT0();
        __syncthreads();
        if (it + 1 < NCH) { issue(it + 1, (it + 1) & 1); CP_COMMIT(); }
        compute_chunk(s0, it & 1, aOff, bOff, acc);
    }

#pragma unroll
    for (int mf = 0; mf < 2; mf++) {
        const int m0 = bm + wm * 32 + mf * 16 + (lane >> 2);
#pragma unroll
        for (int pr = 0; pr < 2; pr++) {
            const int m = m0 + pr * 8;
            float* xrow = g_xw + ((size_t)(m & 127) * Nn + (m >> 7)) * G4;
#pragma unroll
            for (int nf = 0; nf < 4; nf++) {
                const int col = bn + wn * 32 + nf * 8 + (lane & 3) * 2;
                *(float2*)&xrow[col] =
                    make_float2(acc[mf][nf][pr * 2], acc[mf][nf][pr * 2 + 1]);
            }
        }
    }
}

// =====================================================================
// Per-step fused launch:
//   z<2 : GEMM  gp[kz] = h(:, Kz) @ Wh(Kz, :), K=1024 split x2 (256 CTAs)
//   z==2: attention blocks (128 CTAs; each handles 2 n): softmax(A.h/32),
//         then g_pa[n] = sum_l w_l * P[(n,l)]  -- overlapped with GEMM.
// =====================================================================
__global__ __launch_bounds__(256, 3) void gemm_step_kernel(const float* __restrict__ A)
{
    extern __shared__ __align__(128) __nv_bfloat16 dsm[];
    const int tid = threadIdx.x;
    const int lane = tid & 31;

    if (blockIdx.z == 2) {
        // ---------------- attention / P-sum blocks ----------------
        __shared__ float red[16][8];
        __shared__ float wsm[16];
        const int flat = blockIdx.y * 64 + blockIdx.x;   // 0..127
#pragma unroll 1
        for (int sub = 0; sub < 2; sub++) {
            const int n = flat * 2 + sub;
            const float* An = A + (size_t)n * Hh * 16;
            const float* hn = g_h + (size_t)n * Hh;

            float sc[16];
#pragma unroll
            for (int l = 0; l < 16; l++) sc[l] = 0.0f;
#pragma unroll
            for (int r = 0; r < 4; r++) {
                int hh = tid + r * 256;
                float hv = hn[hh];
                const float4* ar = (const float4*)(An + (size_t)hh * 16);
                float4 a0 = ar[0], a1 = ar[1], a2 = ar[2], a3 = ar[3];
                sc[0]  += a0.x * hv; sc[1]  += a0.y * hv; sc[2]  += a0.z * hv; sc[3]  += a0.w * hv;
                sc[4]  += a1.x * hv; sc[5]  += a1.y * hv; sc[6]  += a1.z * hv; sc[7]  += a1.w * hv;
                sc[8]  += a2.x * hv; sc[9]  += a2.y * hv; sc[10] += a2.z * hv; sc[11] += a2.w * hv;
                sc[12] += a3.x * hv; sc[13] += a3.y * hv; sc[14] += a3.z * hv; sc[15] += a3.w * hv;
            }
#pragma unroll
            for (int l = 0; l < 16; l++) {
#pragma unroll
                for (int off = 16; off > 0; off >>= 1)
                    sc[l] += __shfl_xor_sync(0xffffffffu, sc[l], off);
            }
            int warp = tid >> 5;
            if (lane == 0) {
#pragma unroll
                for (int l = 0; l < 16; l++) red[l][warp] = sc[l];
            }
            __syncthreads();
            if (tid == 0) {
                float s[16];
                float mx = -1e30f;
#pragma unroll
                for (int l = 0; l < 16; l++) {
                    float v = 0.0f;
#pragma unroll
                    for (int w2 = 0; w2 < 8; w2++) v += red[l][w2];
                    v *= 0.03125f;  // 1/sqrt(1024)
                    s[l] = v;
                    mx = fmaxf(mx, v);
                }
                float sum = 0.0f;
#pragma unroll
                for (int l = 0; l < 16; l++) { float e = __expf(s[l] - mx); s[l] = e; sum += e; }
                float inv = 1.0f / sum;
#pragma unroll
                for (int l = 0; l < 16; l++) wsm[l] = s[l] * inv;
            }
            __syncthreads();

            float s[16];
#pragma unroll
            for (int i = 0; i < 16; i++) s[i] = 0.0f;
#pragma unroll
            for (int l = 0; l < 16; l++) {
                const float wl = wsm[l];
                const float* Pr = g_P + ((size_t)(n * 16 + l)) * G4;
#pragma unroll
                for (int i = 0; i < 16; i++) s[i] += wl * Pr[tid + i * 256];
            }
            float* pa = g_pa + (size_t)n * G4;
#pragma unroll
            for (int i = 0; i < 16; i++) pa[tid + i * 256] = s[i];
            __syncthreads();
        }
        return;
    }

    // ---------------- GEMM blocks ----------------
    const uint32_t s0 = smem_to_u32(dsm);
    const int w = tid >> 5;
    const int wm = w & 3, wn = w >> 2;
    const int bn = blockIdx.x * GBN;
    const int bm = blockIdx.y * GBM;
    const int kz = blockIdx.z;
    const int kbase = kz * 512;

    const int a_row = tid >> 2, a_seg = tid & 3;
    const int b_row = tid >> 2, b_seg = tid & 3;
    const uint32_t aOff = (uint32_t)((wm * 32 + (lane & 15)) * RSTR + (lane >> 4) * 16);
    const int brow = (lane & 7) + ((lane >> 4) << 3);
    const uint32_t bOff = (uint32_t)((wn * 32 + brow) * RSTR + ((lane >> 3) & 1) * 16);

    auto issue = [&](int c, int s) {
        const int kc = kbase + c * GBK;
        {
            const size_t o = (size_t)(bn + b_row) * Ktot + kc + b_seg * 8;
            CP_ASYNC16(s0 + BH_OFF(s) + b_row * RSTR + b_seg * 16, g_WThi + o);
            CP_ASYNC16(s0 + BL_OFF(s) + b_row * RSTR + b_seg * 16, g_WTlo + o);
        }
#pragma unroll
        for (int r = 0; r < 2; r++) {
            const int m = a_row + r * 64;
            const size_t o = (size_t)(bm + m) * Hh + kc + a_seg * 8;
            const uint32_t d = m * RSTR + a_seg * 16;
            CP_ASYNC16(s0 + AH_OFF(s) + d, g_Ahi + o);
            CP_ASYNC16(s0 + AL_OFF(s) + d, g_Alo + o);
        }
    };

    float acc[2][4][4];
#pragma unroll
    for (int mf = 0; mf < 2; mf++)
#pragma unroll
        for (int nf = 0; nf < 4; nf++)
#pragma unroll
            for (int i = 0; i < 4; i++) acc[mf][nf][i] = 0.0f;

    const int NCH = 512 / GBK;  // 16
    issue(0, 0); CP_COMMIT();
    for (int it = 0; it < NCH; it++) {
        CP_WAIT0();
        __syncthreads();
        if (it + 1 < NCH) { issue(it + 1, (it + 1) & 1); CP_COMMIT(); }
        compute_chunk(s0, it & 1, aOff, bOff, acc);
    }

    float* gpart = g_gp + (size_t)kz * Nn * G4;
#pragma unroll
    for (int mf = 0; mf < 2; mf++) {
        const int row0 = bm + wm * 32 + mf * 16 + (lane >> 2);
#pragma unroll
        for (int nf = 0; nf < 4; nf++) {
            const int col = bn + wn * 32 + nf * 8 + (lane & 3) * 2;
            *(float2*)&gpart[(size_t)row0 * G4 + col] =
                make_float2(acc[mf][nf][0], acc[mf][nf][1]);
            *(float2*)&gpart[(size_t)(row0 + 8) * G4 + col] =
                make_float2(acc[mf][nf][2], acc[mf][nf][3]);
        }
    }
}

// =====================================================================
// Init: h0 = mean_l A[n,h,l]; c0 = h0; write g_h fp32 + bf16 hi/lo.
// =====================================================================
__global__ __launch_bounds__(256) void init_kernel(const float* __restrict__ A)
{
    int n = blockIdx.x;
    int tid = threadIdx.x;
    const float* An = A + (size_t)n * Hh * 16;

#pragma unroll
    for (int r = 0; r < 4; r++) {
        int hh = tid + r * 256;
        const float4* ar = (const float4*)(An + (size_t)hh * 16);
        float4 a0 = ar[0], a1 = ar[1], a2 = ar[2], a3 = ar[3];
        float s = a0.x + a0.y + a0.z + a0.w + a1.x + a1.y + a1.z + a1.w
                + a2.x + a2.y + a2.z + a2.w + a3.x + a3.y + a3.z + a3.w;
        s *= (1.0f / 16.0f);
        g_c[(size_t)n * Hh + hh] = s;
        g_h[(size_t)n * Hh + hh] = s;
        __nv_bfloat16 hi, lo;
        split_bf16(s, hi, lo);
        g_Ahi[(size_t)n * Hh + hh] = hi;
        g_Alo[(size_t)n * Hh + hh] = lo;
    }
}

// =====================================================================
// LSTM pointwise only: gates = gp0+gp1+xw+pa+b -> h,c; emit h fp32+bf16.
// Grid: 1024 blocks x 256 threads (one element per thread).
// =====================================================================
__global__ __launch_bounds__(256) void lstm_kernel(const float* __restrict__ b,
                                                   float* __restrict__ out, int t)
{
    const int e = blockIdx.x * 256 + threadIdx.x;   // 0 .. N*H-1
    const int n = e >> 10;
    const int hh = e & 1023;
    const size_t base = (size_t)n * G4;
    const float* g0 = g_gp + base;
    const float* g1 = g_gp + (size_t)Nn * G4 + base;
    const float* xw = g_xw + ((size_t)t * Nn + n) * G4;
    const float* pa = g_pa + base;

    float gv4[4];
#pragma unroll
    for (int gg = 0; gg < 4; gg++) {
        int o = gg * Hh + hh;
        gv4[gg] = ((g0[o] + g1[o]) + (xw[o] + pa[o])) + b[o];
    }
    float c = g_c[e];
    float cn = sigmoidf_(gv4[1]) * c + sigmoidf_(gv4[0]) * tanhf_(gv4[3]);
    float hn = sigmoidf_(gv4[2]) * tanhf_(cn);
    g_c[e] = cn;
    g_h[e] = hn;
    out[(size_t)n * Tt * Hh + (size_t)t * Hh + hh] = hn;
    __nv_bfloat16 hi, lo;
    split_bf16(hn, hi, lo);
    g_Ahi[e] = hi;
    g_Alo[e] = lo;
}

// =====================================================================
// launch
// =====================================================================
extern "C" void kernel_launch(void* const* d_in, const int* in_sizes, int n_in,
                              void* d_out, int out_size)
{
    (void)in_sizes; (void)n_in; (void)out_size;
    const float* x     = (const float*)d_in[0];  // (N, T, D)
    const float* A     = (const float*)d_in[1];  // (N, H, 4, 4)
    const float* Wx    = (const float*)d_in[2];  // (D, 4H)
    const float* Wh    = (const float*)d_in[3];  // (H, 4H)
    const float* Wattn = (const float*)d_in[4];  // (H, 4H)
    const float* b     = (const float*)d_in[5];  // (4H,)
    float* out = (float*)d_out;                  // (N, T, H)

    cudaFuncSetAttribute(gemm_step_kernel,
                         cudaFuncAttributeMaxDynamicSharedMemorySize, SMEM_DYN);
    cudaFuncSetAttribute(gemm_xw_kernel,
                         cudaFuncAttributeMaxDynamicSharedMemorySize, SMEM_DYN);
    cudaFuncSetAttribute(gemm_P_kernel,
                         cudaFuncAttributeMaxDynamicSharedMemorySize, SMEM_DYN);

    // one-time prep
    dim3 wgrid(G4 / 32, Ktot / 32);
    wconv_kernel<<<wgrid, 256>>>(Wx, Wh, Wattn);
    xconv_kernel<<<8192, 256>>>(x);
    aconv_kernel<<<Nn, 256>>>(A);
    gemm_P_kernel<<<dim3(G4 / GBN, (Nn * 16) / GBM), 256, SMEM_DYN>>>();
    gemm_xw_kernel<<<dim3(G4 / GBN, (Nn * Tt) / GBM), 256, SMEM_DYN>>>();
    init_kernel<<<Nn, 256>>>(A);

    dim3 step_grid(G4 / GBN, Nn / GBM, 3);  // z<2: GEMM (256 CTAs); z==2: attn (128 CTAs)
    for (int t = 0; t < Tt; t++) {
        gemm_step_kernel<<<step_grid, 256, SMEM_DYN>>>(A);
        lstm_kernel<<<(Nn * Hh) / 256, 256>>>(b, out, t);
    }
}

// round 11
// speedup vs baseline: 5.3520x; 1.0266x over previous
#include <cuda_runtime.h>
#include <cuda_bf16.h>
#include <cstdint>
#include <cstddef>

// Problem dims
#define Nn 256
#define Tt 128
#define Dd 512
#define Hh 1024
#define G4 4096            // 4*H
#define Ktot 2560          // W^T cols: Wh (0..1023) | Wattn (1024..2047) | Wx (2048..2559)
#define KSTEP 1536         // per-step GEMM K: h (0..1023) | x_t (1024..1535)

#define NBLK 384           // persistent grid: 256 GEMM + 128 attn CTAs (<= 148*3 resident)

// ---------------- scratch (device globals: allocation-free rule) ----------------
__device__ float g_c[Nn * Hh];                          // LSTM cell state (fp32)
__device__ float g_h[Nn * Hh];                          // current h (fp32)
__device__ float g_gp[(size_t)2 * Nn * G4];             // per-step GEMM partials (2 K-splits)
__device__ float g_pa[(size_t)Nn * G4];                 // attn contribution to gates
__device__ float g_P[(size_t)Nn * 16 * G4];             // P[(n,l)][col] = A[n,:,l] @ Wattn
__device__ __nv_bfloat16 g_Ahi[(size_t)Nn * Hh];        // h hi
__device__ __nv_bfloat16 g_Alo[(size_t)Nn * Hh];        // h lo
__device__ __nv_bfloat16 g_AThi[(size_t)Nn * 16 * Hh];  // A^T [(n,l)][h] hi
__device__ __nv_bfloat16 g_ATlo[(size_t)Nn * 16 * Hh];  // A^T [(n,l)][h] lo
__device__ __nv_bfloat16 g_xhi[(size_t)Nn * Tt * Dd];   // x hi
__device__ __nv_bfloat16 g_xlo[(size_t)Nn * Tt * Dd];   // x lo
__device__ __nv_bfloat16 g_WThi[(size_t)G4 * Ktot];     // W^T hi: [n][k], K-major
__device__ __nv_bfloat16 g_WTlo[(size_t)G4 * Ktot];     // W^T lo

// grid barrier state (persists across launches; only gen value carries over — harmless)
__device__ unsigned g_bar_count = 0;
__device__ unsigned g_bar_gen = 0;

// ---------------- PTX helpers (sm_80+ baseline features only) ----------------
__device__ __forceinline__ uint32_t smem_to_u32(const void* p) {
    uint32_t a;
    asm("{ .reg .u64 t; cvta.to.shared.u64 t, %1; cvt.u32.u64 %0, t; }" : "=r"(a) : "l"(p));
    return a;
}
#define CP_ASYNC16(dst, src) \
    asm volatile("cp.async.cg.shared.global [%0], [%1], 16;" :: "r"(dst), "l"(src))
#define CP_COMMIT() asm volatile("cp.async.commit_group;" ::: "memory")
#define CP_WAIT0()  asm volatile("cp.async.wait_group 0;" ::: "memory")
#define LDSM_X4(r0, r1, r2, r3, addr)                                             \
    asm volatile("ldmatrix.sync.aligned.m8n8.x4.shared.b16 {%0,%1,%2,%3}, [%4];"  \
        : "=r"(r0), "=r"(r1), "=r"(r2), "=r"(r3) : "r"(addr))

__device__ __forceinline__ void mma16816(float* c, const uint32_t* a,
                                         uint32_t b0, uint32_t b1) {
    asm volatile(
        "mma.sync.aligned.m16n8k16.row.col.f32.bf16.bf16.f32 "
        "{%0,%1,%2,%3}, {%4,%5,%6,%7}, {%8,%9}, {%0,%1,%2,%3};"
        : "+f"(c[0]), "+f"(c[1]), "+f"(c[2]), "+f"(c[3])
        : "r"(a[0]), "r"(a[1]), "r"(a[2]), "r"(a[3]), "r"(b0), "r"(b1));
}

// Software grid barrier. Safe because all NBLK CTAs are co-resident (grid <= 1 wave).
__device__ __forceinline__ void grid_sync() {
    __syncthreads();
    if (threadIdx.x == 0) {
        __threadfence();
        unsigned g = *(volatile unsigned*)&g_bar_gen;
        unsigned prev = atomicAdd(&g_bar_count, 1u);
        if (prev == NBLK - 1) {
            g_bar_count = 0;
            __threadfence();
            *(volatile unsigned*)&g_bar_gen = g + 1;
        } else {
            while (*(volatile unsigned*)&g_bar_gen == g) { __nanosleep(64); }
        }
    }
    __syncthreads();
}

// ---------------- math helpers ----------------
__device__ __forceinline__ float sigmoidf_(float x) { return 1.0f / (1.0f + __expf(-x)); }
__device__ __forceinline__ float tanhf_(float x) {
    float e = __expf(2.0f * x);
    return 1.0f - 2.0f / (e + 1.0f);
}
__device__ __forceinline__ void split_bf16(float v, __nv_bfloat16& hi, __nv_bfloat16& lo) {
    hi = __float2bfloat16(v);
    lo = __float2bfloat16(v - __bfloat162float(hi));
}

// ---------------- shared GEMM tiling ----------------
#define GBM 128
#define GBN 64
#define GBK 32
#define RSTR 80              // smem row stride bytes (32 bf16 + 8 pad)
#define STG 30720            // bytes per pipeline stage
#define AH_OFF(s) ((s) * STG)
#define AL_OFF(s) ((s) * STG + 10240)
#define BH_OFF(s) ((s) * STG + 20480)
#define BL_OFF(s) ((s) * STG + 25600)
#define SMEM_DYN (2 * STG)   // 61440 -> 3 CTAs/SM

// Fragment compute for one chunk stage.
__device__ __forceinline__ void compute_chunk(uint32_t s0, int stage,
                                              uint32_t aOff, uint32_t bOff,
                                              float acc[2][4][4])
{
    const uint32_t ah = s0 + AH_OFF(stage) + aOff;
    const uint32_t al = s0 + AL_OFF(stage) + aOff;
    const uint32_t bh = s0 + BH_OFF(stage) + bOff;
    const uint32_t bl = s0 + BL_OFF(stage) + bOff;
#pragma unroll
    for (int ks = 0; ks < 2; ks++) {
        const uint32_t ko = ks * 32;   // 16 elems * 2B
        uint32_t ahf[2][4], alf[2][4];
        uint32_t bhf[2][4], blf[2][4];
        LDSM_X4(ahf[0][0], ahf[0][1], ahf[0][2], ahf[0][3], ah + ko);
        LDSM_X4(ahf[1][0], ahf[1][1], ahf[1][2], ahf[1][3], ah + 16 * RSTR + ko);
        LDSM_X4(bhf[0][0], bhf[0][1], bhf[0][2], bhf[0][3], bh + ko);
        LDSM_X4(bhf[1][0], bhf[1][1], bhf[1][2], bhf[1][3], bh + 16 * RSTR + ko);
        LDSM_X4(blf[0][0], blf[0][1], blf[0][2], blf[0][3], bl + ko);
        LDSM_X4(blf[1][0], blf[1][1], blf[1][2], blf[1][3], bl + 16 * RSTR + ko);
        LDSM_X4(alf[0][0], alf[0][1], alf[0][2], alf[0][3], al + ko);
        LDSM_X4(alf[1][0], alf[1][1], alf[1][2], alf[1][3], al + 16 * RSTR + ko);
#pragma unroll
        for (int mf = 0; mf < 2; mf++) {
#pragma unroll
            for (int nf = 0; nf < 4; nf++) {
                const uint32_t b0 = bhf[nf >> 1][(nf & 1) * 2];
                const uint32_t b1 = bhf[nf >> 1][(nf & 1) * 2 + 1];
                mma16816(acc[mf][nf], ahf[mf], b0, b1);           // hi*hi
                mma16816(acc[mf][nf], alf[mf], b0, b1);           // lo*hi
                mma16816(acc[mf][nf], ahf[mf],                    // hi*lo
                         blf[nf >> 1][(nf & 1) * 2], blf[nf >> 1][(nf & 1) * 2 + 1]);
            }
        }
    }
}

// =====================================================================
// One-time: W^T hi/lo. WT[n][k] = bf16split(W[k][n]); K rows: Wh|Wattn|Wx
// =====================================================================
__global__ __launch_bounds__(256) void wconv_kernel(const float* __restrict__ Wx,
                                                    const float* __restrict__ Wh,
                                                    const float* __restrict__ Wattn)
{
    __shared__ float tile[32][33];
    const int nt = blockIdx.x * 32;
    const int kt = blockIdx.y * 32;
    const int tx = threadIdx.x & 31, ty = threadIdx.x >> 5;
#pragma unroll
    for (int r = 0; r < 4; r++) {
        int k = kt + ty + r * 8;
        int n = nt + tx;
        const float* src;
        if (k < 1024)       src = Wh    + (size_t)k * G4;
        else if (k < 2048)  src = Wattn + (size_t)(k - 1024) * G4;
        else                src = Wx    + (size_t)(k - 2048) * G4;
        tile[ty + r * 8][tx] = src[n];
    }
    __syncthreads();
#pragma unroll
    for (int r = 0; r < 4; r++) {
        int n = nt + ty + r * 8;
        int k = kt + tx;
        float v = tile[tx][ty + r * 8];
        __nv_bfloat16 hi, lo;
        split_bf16(v, hi, lo);
        g_WThi[(size_t)n * Ktot + k] = hi;
        g_WTlo[(size_t)n * Ktot + k] = lo;
    }
}

// One-time: x -> bf16 hi/lo
__global__ __launch_bounds__(256) void xconv_kernel(const float* __restrict__ x)
{
    const size_t total = (size_t)Nn * Tt * Dd;
    for (size_t i = (size_t)blockIdx.x * blockDim.x + threadIdx.x; i < total;
         i += (size_t)gridDim.x * blockDim.x) {
        __nv_bfloat16 hi, lo;
        split_bf16(x[i], hi, lo);
        g_xhi[i] = hi;
        g_xlo[i] = lo;
    }
}

// One-time: A[n][h][l] -> A^T [(n*16+l)][h] bf16 hi/lo
__global__ __launch_bounds__(256) void aconv_kernel(const float* __restrict__ A)
{
    const int n = blockIdx.x;
    const float* An = A + (size_t)n * Hh * 16;
    for (int idx = threadIdx.x; idx < Hh * 16; idx += 256) {
        const int h = idx >> 4, l = idx & 15;
        __nv_bfloat16 hi, lo;
        split_bf16(An[idx], hi, lo);
        const size_t o = ((size_t)(n * 16 + l)) * Hh + h;
        g_AThi[o] = hi;
        g_ATlo[o] = lo;
    }
}

// =====================================================================
// One-time GEMM: P[(n,l)][:] = A^T[(n,l)][:] @ Wattn  (bf16 hi/lo x3)
// =====================================================================
__global__ __launch_bounds__(256, 3) void gemm_P_kernel()
{
    extern __shared__ __align__(128) __nv_bfloat16 dsm[];
    const uint32_t s0 = smem_to_u32(dsm);
    const int tid = threadIdx.x;
    const int lane = tid & 31;
    const int w = tid >> 5;
    const int wm = w & 3, wn = w >> 2;
    const int bn = blockIdx.x * GBN;
    const int bm = blockIdx.y * GBM;

    const int a_row = tid >> 2, a_seg = tid & 3;
    const int b_row = tid >> 2, b_seg = tid & 3;
    const uint32_t aOff = (uint32_t)((wm * 32 + (lane & 15)) * RSTR + (lane >> 4) * 16);
    const int brow = (lane & 7) + ((lane >> 4) << 3);
    const uint32_t bOff = (uint32_t)((wn * 32 + brow) * RSTR + ((lane >> 3) & 1) * 16);

    auto issue = [&](int c, int s) {
        const int kc = c * GBK;
        {
            const size_t o = (size_t)(bn + b_row) * Ktot + 1024 + kc + b_seg * 8;
            CP_ASYNC16(s0 + BH_OFF(s) + b_row * RSTR + b_seg * 16, g_WThi + o);
            CP_ASYNC16(s0 + BL_OFF(s) + b_row * RSTR + b_seg * 16, g_WTlo + o);
        }
#pragma unroll
        for (int r = 0; r < 2; r++) {
            const int m = a_row + r * 64;
            const size_t o = (size_t)(bm + m) * Hh + kc + a_seg * 8;
            const uint32_t d = m * RSTR + a_seg * 16;
            CP_ASYNC16(s0 + AH_OFF(s) + d, g_AThi + o);
            CP_ASYNC16(s0 + AL_OFF(s) + d, g_ATlo + o);
        }
    };

    float acc[2][4][4];
#pragma unroll
    for (int mf = 0; mf < 2; mf++)
#pragma unroll
        for (int nf = 0; nf < 4; nf++)
#pragma unroll
            for (int i = 0; i < 4; i++) acc[mf][nf][i] = 0.0f;

    const int NCH = Hh / GBK;  // 32
    issue(0, 0); CP_COMMIT();
    for (int it = 0; it < NCH; it++) {
        CP_WAIT0();
        __syncthreads();
        if (it + 1 < NCH) { issue(it + 1, (it + 1) & 1); CP_COMMIT(); }
        compute_chunk(s0, it & 1, aOff, bOff, acc);
    }

#pragma unroll
    for (int mf = 0; mf < 2; mf++) {
        const int row0 = bm + wm * 32 + mf * 16 + (lane >> 2);
#pragma unroll
        for (int nf = 0; nf < 4; nf++) {
            const int col = bn + wn * 32 + nf * 8 + (lane & 3) * 2;
            *(float2*)&g_P[(size_t)row0 * G4 + col] =
                make_float2(acc[mf][nf][0], acc[mf][nf][1]);
            *(float2*)&g_P[(size_t)(row0 + 8) * G4 + col] =
                make_float2(acc[mf][nf][2], acc[mf][nf][3]);
        }
    }
}

// =====================================================================
// Init: h0 = mean_l A[n,h,l]; c0 = h0; write g_h fp32 + bf16 hi/lo.
// =====================================================================
__global__ __launch_bounds__(256) void init_kernel(const float* __restrict__ A)
{
    int n = blockIdx.x;
    int tid = threadIdx.x;
    const float* An = A + (size_t)n * Hh * 16;

#pragma unroll
    for (int r = 0; r < 4; r++) {
        int hh = tid + r * 256;
        const float4* ar = (const float4*)(An + (size_t)hh * 16);
        float4 a0 = ar[0], a1 = ar[1], a2 = ar[2], a3 = ar[3];
        float s = a0.x + a0.y + a0.z + a0.w + a1.x + a1.y + a1.z + a1.w
                + a2.x + a2.y + a2.z + a2.w + a3.x + a3.y + a3.z + a3.w;
        s *= (1.0f / 16.0f);
        g_c[(size_t)n * Hh + hh] = s;
        g_h[(size_t)n * Hh + hh] = s;
        __nv_bfloat16 hi, lo;
        split_bf16(s, hi, lo);
        g_Ahi[(size_t)n * Hh + hh] = hi;
        g_Alo[(size_t)n * Hh + hh] = lo;
    }
}

// =====================================================================
// Persistent step loop: 384 CTAs, all resident.
//   bx <  256: GEMM  gp[kz] = [h|x_t](:, Kz) @ [Wh;Wx](Kz, :), K=1536 split x2
//   bx >= 256: attention (2 n each): softmax(A.h/32); g_pa = sum_l w_l P[(n,l)]
//   then grid_sync; cooperative LSTM pointwise; grid_sync; next t.
// =====================================================================
__global__ __launch_bounds__(256, 3) void step_loop_kernel(const float* __restrict__ A,
                                                           const float* __restrict__ b,
                                                           float* __restrict__ out)
{
    extern __shared__ __align__(128) __nv_bfloat16 dsm[];
    __shared__ float red[16][8];
    __shared__ float wsm[16];

    const uint32_t s0 = smem_to_u32(dsm);
    const int tid = threadIdx.x;
    const int lane = tid & 31;
    const int bx = blockIdx.x;

    // GEMM-role constants
    const int w = tid >> 5;
    const int wm = w & 3, wn = w >> 2;
    const int bn = (bx & 63) * GBN;
    const int bm = ((bx >> 6) & 1) * GBM;
    const int kz = (bx >> 7) & 1;
    const int kbase = kz * (KSTEP / 2);      // 0 or 768
    const int a_row = tid >> 2, a_seg = tid & 3;
    const int b_row = tid >> 2, b_seg = tid & 3;
    const uint32_t aOff = (uint32_t)((wm * 32 + (lane & 15)) * RSTR + (lane >> 4) * 16);
    const int brow_l = (lane & 7) + ((lane >> 4) << 3);
    const uint32_t bOff = (uint32_t)((wn * 32 + brow_l) * RSTR + ((lane >> 3) & 1) * 16);

    for (int t = 0; t < Tt; t++) {
        if (bx < 256) {
            // ---------------- GEMM role ----------------
            auto issue = [&](int c, int s) {
                const int kg = kbase + c * GBK;                    // 0..1535
                const int kidx = (kg < 1024) ? kg : kg + 1024;     // WT column
                {
                    const size_t o = (size_t)(bn + b_row) * Ktot + kidx + b_seg * 8;
                    CP_ASYNC16(s0 + BH_OFF(s) + b_row * RSTR + b_seg * 16, g_WThi + o);
                    CP_ASYNC16(s0 + BL_OFF(s) + b_row * RSTR + b_seg * 16, g_WTlo + o);
                }
#pragma unroll
                for (int r = 0; r < 2; r++) {
                    const int m = a_row + r * 64;
                    const __nv_bfloat16 *sh, *sl;
                    if (kg < 1024) {
                        const size_t o = (size_t)(bm + m) * Hh + kg + a_seg * 8;
                        sh = g_Ahi + o; sl = g_Alo + o;
                    } else {
                        const size_t o = (size_t)(bm + m) * (Tt * Dd) + (size_t)t * Dd
                                       + (kg - 1024) + a_seg * 8;
                        sh = g_xhi + o; sl = g_xlo + o;
                    }
                    const uint32_t d = m * RSTR + a_seg * 16;
                    CP_ASYNC16(s0 + AH_OFF(s) + d, sh);
                    CP_ASYNC16(s0 + AL_OFF(s) + d, sl);
                }
            };

            float acc[2][4][4];
#pragma unroll
            for (int mf = 0; mf < 2; mf++)
#pragma unroll
                for (int nf = 0; nf < 4; nf++)
#pragma unroll
                    for (int i = 0; i < 4; i++) acc[mf][nf][i] = 0.0f;

            const int NCH = (KSTEP / 2) / GBK;  // 24
            issue(0, 0); CP_COMMIT();
            for (int it = 0; it < NCH; it++) {
                CP_WAIT0();
                __syncthreads();
                if (it + 1 < NCH) { issue(it + 1, (it + 1) & 1); CP_COMMIT(); }
                compute_chunk(s0, it & 1, aOff, bOff, acc);
            }

            float* gpart = g_gp + (size_t)kz * Nn * G4;
#pragma unroll
            for (int mf = 0; mf < 2; mf++) {
                const int row0 = bm + wm * 32 + mf * 16 + (lane >> 2);
#pragma unroll
                for (int nf = 0; nf < 4; nf++) {
                    const int col = bn + wn * 32 + nf * 8 + (lane & 3) * 2;
                    *(float2*)&gpart[(size_t)row0 * G4 + col] =
                        make_float2(acc[mf][nf][0], acc[mf][nf][1]);
                    *(float2*)&gpart[(size_t)(row0 + 8) * G4 + col] =
                        make_float2(acc[mf][nf][2], acc[mf][nf][3]);
                }
            }
        } else {
            // ---------------- attention / P-sum role ----------------
            const int flat = bx - 256;   // 0..127
#pragma unroll 1
            for (int sub = 0; sub < 2; sub++) {
                const int n = flat * 2 + sub;
                const float* An = A + (size_t)n * Hh * 16;
                const float* hn = g_h + (size_t)n * Hh;

                float sc[16];
#pragma unroll
                for (int l = 0; l < 16; l++) sc[l] = 0.0f;
#pragma unroll
                for (int r = 0; r < 4; r++) {
                    int hh = tid + r * 256;
                    float hv = hn[hh];
                    const float4* ar = (const float4*)(An + (size_t)hh * 16);
                    float4 a0 = ar[0], a1 = ar[1], a2 = ar[2], a3 = ar[3];
                    sc[0]  += a0.x * hv; sc[1]  += a0.y * hv; sc[2]  += a0.z * hv; sc[3]  += a0.w * hv;
                    sc[4]  += a1.x * hv; sc[5]  += a1.y * hv; sc[6]  += a1.z * hv; sc[7]  += a1.w * hv;
                    sc[8]  += a2.x * hv; sc[9]  += a2.y * hv; sc[10] += a2.z * hv; sc[11] += a2.w * hv;
                    sc[12] += a3.x * hv; sc[13] += a3.y * hv; sc[14] += a3.z * hv; sc[15] += a3.w * hv;
                }
#pragma unroll
                for (int l = 0; l < 16; l++) {
#pragma unroll
                    for (int off = 16; off > 0; off >>= 1)
                        sc[l] += __shfl_xor_sync(0xffffffffu, sc[l], off);
                }
                int warp = tid >> 5;
                if (lane == 0) {
#pragma unroll
                    for (int l = 0; l < 16; l++) red[l][warp] = sc[l];
                }
                __syncthreads();
                if (tid == 0) {
                    float s[16];
                    float mx = -1e30f;
#pragma unroll
                    for (int l = 0; l < 16; l++) {
                        float v = 0.0f;
#pragma unroll
                        for (int w2 = 0; w2 < 8; w2++) v += red[l][w2];
                        v *= 0.03125f;  // 1/sqrt(1024)
                        s[l] = v;
                        mx = fmaxf(mx, v);
                    }
                    float sum = 0.0f;
#pragma unroll
                    for (int l = 0; l < 16; l++) { float e = __expf(s[l] - mx); s[l] = e; sum += e; }
                    float inv = 1.0f / sum;
#pragma unroll
                    for (int l = 0; l < 16; l++) wsm[l] = s[l] * inv;
                }
                __syncthreads();

                float s[16];
#pragma unroll
                for (int i = 0; i < 16; i++) s[i] = 0.0f;
#pragma unroll
                for (int l = 0; l < 16; l++) {
                    const float wl = wsm[l];
                    const float* Pr = g_P + ((size_t)(n * 16 + l)) * G4;
#pragma unroll
                    for (int i = 0; i < 16; i++) s[i] += wl * Pr[tid + i * 256];
                }
                float* pa = g_pa + (size_t)n * G4;
#pragma unroll
                for (int i = 0; i < 16; i++) pa[tid + i * 256] = s[i];
                __syncthreads();
            }
        }

        grid_sync();   // gp + pa complete and visible

        // ---------------- cooperative LSTM pointwise ----------------
        for (int e = bx * 256 + tid; e < Nn * Hh; e += NBLK * 256) {
            const int n = e >> 10;
            const int hh = e & 1023;
            const size_t base = (size_t)n * G4;
            const float* g0 = g_gp + base;
            const float* g1 = g_gp + (size_t)Nn * G4 + base;
            const float* pa = g_pa + base;
            float gv[4];
#pragma unroll
            for (int gg = 0; gg < 4; gg++) {
                const int o = gg * Hh + hh;
                gv[gg] = (g0[o] + g1[o]) + (pa[o] + b[o]);
            }
            float c = g_c[e];
            float cn = sigmoidf_(gv[1]) * c + sigmoidf_(gv[0]) * tanhf_(gv[3]);
            float hn = sigmoidf_(gv[2]) * tanhf_(cn);
            g_c[e] = cn;
            g_h[e] = hn;
            out[(size_t)n * Tt * Hh + (size_t)t * Hh + hh] = hn;
            __nv_bfloat16 hi, lo;
            split_bf16(hn, hi, lo);
            g_Ahi[e] = hi;
            g_Alo[e] = lo;
        }

        grid_sync();   // h_{t+1} visible to everyone
    }
}

// =====================================================================
// launch
// =====================================================================
extern "C" void kernel_launch(void* const* d_in, const int* in_sizes, int n_in,
                              void* d_out, int out_size)
{
    (void)in_sizes; (void)n_in; (void)out_size;
    const float* x     = (const float*)d_in[0];  // (N, T, D)
    const float* A     = (const float*)d_in[1];  // (N, H, 4, 4)
    const float* Wx    = (const float*)d_in[2];  // (D, 4H)
    const float* Wh    = (const float*)d_in[3];  // (H, 4H)
    const float* Wattn = (const float*)d_in[4];  // (H, 4H)
    const float* b     = (const float*)d_in[5];  // (4H,)
    float* out = (float*)d_out;                  // (N, T, H)

    cudaFuncSetAttribute(gemm_P_kernel,
                         cudaFuncAttributeMaxDynamicSharedMemorySize, SMEM_DYN);
    cudaFuncSetAttribute(step_loop_kernel,
                         cudaFuncAttributeMaxDynamicSharedMemorySize, SMEM_DYN);

    // one-time prep
    dim3 wgrid(G4 / 32, Ktot / 32);
    wconv_kernel<<<wgrid, 256>>>(Wx, Wh, Wattn);
    xconv_kernel<<<8192, 256>>>(x);
    aconv_kernel<<<Nn, 256>>>(A);
    gemm_P_kernel<<<dim3(G4 / GBN, (Nn * 16) / GBM), 256, SMEM_DYN>>>();
    init_kernel<<<Nn, 256>>>(A);

    // the whole 128-step recurrence in ONE persistent launch
    step_loop_kernel<<<NBLK, 256, SMEM_DYN>>>(A, b, out);
}